// round 6
// baseline (speedup 1.0000x reference)
#include <cuda_runtime.h>
#include <math.h>

// ---------------------------------------------------------------------------
// FastVecKM: out = normalize_rows( complex-demodulated (eB (eB^T eA)) )
//   N=65536 pts, ENC_DIM=512 (2D=1024), P=4096 (2P=8192)
// Two fp32 GEMMs (~2.2 TFLOP) + trig encode + elementwise finalize.
// Scratch kept to 2.29 GB total so aarch64 host-shadow .bss relocations fit.
// ---------------------------------------------------------------------------

#define NPTS   65536
#define DENC   512
#define PDIM   4096
#define TWO_D  1024
#define TWO_P  8192

#define BM 128
#define BN 128
#define BK 16

typedef unsigned long long u64;

// Scratch (allocation-free __device__ globals)
__device__ float g_eA[(u64)NPTS * TWO_D];    // 256 MB : N x 1024, n-major (cos|sin of pA)
__device__ float g_eB[(u64)NPTS * TWO_P];    // 2 GB   : N x 8192, n-major (cos|sin of pB)
__device__ float g_C1[(u64)TWO_P * TWO_D];   // 32 MB  : M = eB^T eA  (8192 x 1024)

// ---- packed fp32 helpers (sm_103a FFMA2) ----------------------------------
__device__ __forceinline__ u64 ffma2(u64 a, u64 b, u64 c) {
    u64 d;
    asm("fma.rn.f32x2 %0, %1, %2, %3;" : "=l"(d) : "l"(a), "l"(b), "l"(c));
    return d;
}
__device__ __forceinline__ u64 dup2(float x) {
    u64 r;
    asm("mov.b64 %0, {%1, %2};" : "=l"(r) : "f"(x), "f"(x));
    return r;
}
__device__ __forceinline__ float2 unpack2(u64 v) {
    float2 r;
    asm("mov.b64 {%0, %1}, %2;" : "=f"(r.x), "=f"(r.y) : "l"(v));
    return r;
}

// ---------------------------------------------------------------------------
// Encode: E[n][j] = cos(ph), E[n][D+j] = sin(ph), ph = (pts[n]/0.05) . W[:,j]
// n-major (row-major N x 2D). j fastest -> coalesced stores.
// ---------------------------------------------------------------------------
__global__ void encode_cols(const float* __restrict__ pts, const float* __restrict__ W,
                            float* __restrict__ E, int D, int logD)
{
    long long idx = (long long)blockIdx.x * blockDim.x + threadIdx.x;
    int n = (int)(idx >> logD);
    int j = (int)(idx & (D - 1));
    float x0 = pts[3 * n + 0] * 20.0f;   // 1/RADIUS
    float x1 = pts[3 * n + 1] * 20.0f;
    float x2 = pts[3 * n + 2] * 20.0f;
    float ph = x0 * W[j] + x1 * W[D + j] + x2 * W[2 * D + j];
    float s, c;
    sincosf(ph, &s, &c);
    u64 base = (u64)n * (u64)(2 * D);
    E[base + j]     = c;
    E[base + D + j] = s;
}

// ---------------------------------------------------------------------------
// Shared FFMA2 microkernel body (reads As/Bs K-major slabs).
// acc: 8 m-rows x 4 packed-f32x2 n-cols per thread.
// ---------------------------------------------------------------------------
#define MICRO_KSTEP(ASB, BSB, k)                                              \
    {                                                                         \
        float4 a0 = *(const float4*)&ASB[k][am];                              \
        float4 a1 = *(const float4*)&ASB[k][am + 4];                          \
        ulonglong2 t0 = *(const ulonglong2*)&BSB[k][bn];                      \
        ulonglong2 t1 = *(const ulonglong2*)&BSB[k][bn + 4];                  \
        u64 bb0 = t0.x, bb1 = t0.y, bb2 = t1.x, bb3 = t1.y;                   \
        u64 ad;                                                               \
        GEMM_ROW(0, a0.x) GEMM_ROW(1, a0.y) GEMM_ROW(2, a0.z) GEMM_ROW(3, a0.w) \
        GEMM_ROW(4, a1.x) GEMM_ROW(5, a1.y) GEMM_ROW(6, a1.z) GEMM_ROW(7, a1.w) \
    }

#define GEMM_ROW(i, av) ad = dup2(av);            \
    acc[i][0] = ffma2(ad, bb0, acc[i][0]);        \
    acc[i][1] = ffma2(ad, bb1, acc[i][1]);        \
    acc[i][2] = ffma2(ad, bb2, acc[i][2]);        \
    acc[i][3] = ffma2(ad, bb3, acc[i][3]);

// ---------------------------------------------------------------------------
// TN SGEMM:  C[m][n] = sum_k A[k*lda + m] * B[k*ldb + n]
// Both operands K-major. 128x128x16, 256 thr, 8x8 microtile, double buffer.
// ---------------------------------------------------------------------------
__global__ __launch_bounds__(256, 2)
void gemm_tn(const float* __restrict__ A, const float* __restrict__ B,
             float* __restrict__ C, int K, int lda, int ldb, int ldc)
{
    __shared__ __align__(16) float As[2][BK][BM];
    __shared__ __align__(16) float Bs[2][BK][BN];

    const int tid = threadIdx.x;
    const int m0 = blockIdx.y * BM;
    const int n0 = blockIdx.x * BN;

    const int lr = tid >> 5;             // 0..7  (k row)
    const int lc = (tid & 31) << 2;      // 0..124 (float4 col)

    const float* aPtr = A + (size_t)lr * lda + (size_t)(m0 + lc);
    const float* bPtr = B + (size_t)lr * ldb + (size_t)(n0 + lc);
    const size_t aStep = (size_t)BK * lda, bStep = (size_t)BK * ldb;
    const size_t a8 = (size_t)8 * lda,    b8 = (size_t)8 * ldb;

    const int am = (tid >> 4) << 3;
    const int bn = (tid & 15) << 3;

    u64 acc[8][4];
#pragma unroll
    for (int i = 0; i < 8; i++)
#pragma unroll
        for (int j = 0; j < 4; j++) acc[i][j] = 0ull;

    float4 ra0 = *(const float4*)(aPtr);
    float4 ra1 = *(const float4*)(aPtr + a8);
    float4 rb0 = *(const float4*)(bPtr);
    float4 rb1 = *(const float4*)(bPtr + b8);
    *(float4*)&As[0][lr][lc]     = ra0;
    *(float4*)&As[0][lr + 8][lc] = ra1;
    *(float4*)&Bs[0][lr][lc]     = rb0;
    *(float4*)&Bs[0][lr + 8][lc] = rb1;
    __syncthreads();

    const int nk = K / BK;
    int buf = 0;
    for (int kt = 0; kt < nk; kt++) {
        if (kt + 1 < nk) {
            const float* ap = aPtr + (size_t)(kt + 1) * aStep;
            const float* bp = bPtr + (size_t)(kt + 1) * bStep;
            ra0 = *(const float4*)(ap);
            ra1 = *(const float4*)(ap + a8);
            rb0 = *(const float4*)(bp);
            rb1 = *(const float4*)(bp + b8);
        }
#pragma unroll
        for (int k = 0; k < BK; k++) MICRO_KSTEP(As[buf], Bs[buf], k)
        if (kt + 1 < nk) {
            int nb = buf ^ 1;
            *(float4*)&As[nb][lr][lc]     = ra0;
            *(float4*)&As[nb][lr + 8][lc] = ra1;
            *(float4*)&Bs[nb][lr][lc]     = rb0;
            *(float4*)&Bs[nb][lr + 8][lc] = rb1;
        }
        __syncthreads();
        buf ^= 1;
    }

    float* cPtr = C + (size_t)(m0 + am) * ldc + (size_t)(n0 + bn);
#pragma unroll
    for (int i = 0; i < 8; i++) {
        float2 p0 = unpack2(acc[i][0]);
        float2 p1 = unpack2(acc[i][1]);
        float2 p2 = unpack2(acc[i][2]);
        float2 p3 = unpack2(acc[i][3]);
        *(float4*)(cPtr)     = make_float4(p0.x, p0.y, p1.x, p1.y);
        *(float4*)(cPtr + 4) = make_float4(p2.x, p2.y, p3.x, p3.y);
        cPtr += ldc;
    }
}

// ---------------------------------------------------------------------------
// NN SGEMM:  C[m][n] = sum_k A[m*lda + k] * B[k*ldb + n]
// A is row(m)-major; transposing loader stages it into K-major smem.
// ---------------------------------------------------------------------------
__global__ __launch_bounds__(256, 2)
void gemm_nn(const float* __restrict__ A, const float* __restrict__ B,
             float* __restrict__ C, int K, int lda, int ldb, int ldc)
{
    __shared__ __align__(16) float As[2][BK][BM];
    __shared__ __align__(16) float Bs[2][BK][BN];

    const int tid = threadIdx.x;
    const int m0 = blockIdx.y * BM;
    const int n0 = blockIdx.x * BN;

    // A loader: rows ar, ar+64 of the 128-row M-slab; 4 k-cols each
    const int ar = tid >> 2;             // 0..63
    const int ac = (tid & 3) << 2;       // 0,4,8,12
    const float* aPtr = A + (size_t)(m0 + ar) * lda + (size_t)ac;
    const size_t a64 = (size_t)64 * lda;

    // B loader: same as TN
    const int lr = tid >> 5;
    const int lc = (tid & 31) << 2;
    const float* bPtr = B + (size_t)lr * ldb + (size_t)(n0 + lc);
    const size_t bStep = (size_t)BK * ldb;
    const size_t b8 = (size_t)8 * ldb;

    const int am = (tid >> 4) << 3;
    const int bn = (tid & 15) << 3;

    u64 acc[8][4];
#pragma unroll
    for (int i = 0; i < 8; i++)
#pragma unroll
        for (int j = 0; j < 4; j++) acc[i][j] = 0ull;

    float4 ra0 = *(const float4*)(aPtr);
    float4 ra1 = *(const float4*)(aPtr + a64);
    float4 rb0 = *(const float4*)(bPtr);
    float4 rb1 = *(const float4*)(bPtr + b8);
    As[0][ac + 0][ar] = ra0.x; As[0][ac + 1][ar] = ra0.y;
    As[0][ac + 2][ar] = ra0.z; As[0][ac + 3][ar] = ra0.w;
    As[0][ac + 0][ar + 64] = ra1.x; As[0][ac + 1][ar + 64] = ra1.y;
    As[0][ac + 2][ar + 64] = ra1.z; As[0][ac + 3][ar + 64] = ra1.w;
    *(float4*)&Bs[0][lr][lc]     = rb0;
    *(float4*)&Bs[0][lr + 8][lc] = rb1;
    __syncthreads();

    const int nk = K / BK;
    int buf = 0;
    for (int kt = 0; kt < nk; kt++) {
        if (kt + 1 < nk) {
            const float* ap = aPtr + (size_t)(kt + 1) * BK;
            const float* bp = bPtr + (size_t)(kt + 1) * bStep;
            ra0 = *(const float4*)(ap);
            ra1 = *(const float4*)(ap + a64);
            rb0 = *(const float4*)(bp);
            rb1 = *(const float4*)(bp + b8);
        }
#pragma unroll
        for (int k = 0; k < BK; k++) MICRO_KSTEP(As[buf], Bs[buf], k)
        if (kt + 1 < nk) {
            int nb = buf ^ 1;
            As[nb][ac + 0][ar] = ra0.x; As[nb][ac + 1][ar] = ra0.y;
            As[nb][ac + 2][ar] = ra0.z; As[nb][ac + 3][ar] = ra0.w;
            As[nb][ac + 0][ar + 64] = ra1.x; As[nb][ac + 1][ar + 64] = ra1.y;
            As[nb][ac + 2][ar + 64] = ra1.z; As[nb][ac + 3][ar + 64] = ra1.w;
            *(float4*)&Bs[nb][lr][lc]     = rb0;
            *(float4*)&Bs[nb][lr + 8][lc] = rb1;
        }
        __syncthreads();
        buf ^= 1;
    }

    float* cPtr = C + (size_t)(m0 + am) * ldc + (size_t)(n0 + bn);
#pragma unroll
    for (int i = 0; i < 8; i++) {
        float2 p0 = unpack2(acc[i][0]);
        float2 p1 = unpack2(acc[i][1]);
        float2 p2 = unpack2(acc[i][2]);
        float2 p3 = unpack2(acc[i][3]);
        *(float4*)(cPtr)     = make_float4(p0.x, p0.y, p1.x, p1.y);
        *(float4*)(cPtr + 4) = make_float4(p2.x, p2.y, p3.x, p3.y);
        cPtr += ldc;
    }
}

// ---------------------------------------------------------------------------
// Finalize (in place on G = d_out): re/im, per-row L2 norm, scale.
// ---------------------------------------------------------------------------
__global__ void finalize_kernel(float* __restrict__ G, const float* __restrict__ eA)
{
    __shared__ float red[256];
    int n = blockIdx.x;
    int t = threadIdx.x;
    u64 base = (u64)n * TWO_D;

    float re[2], im[2];
    float acc = 0.f;
#pragma unroll
    for (int q = 0; q < 2; q++) {
        int j = t + q * 256;
        float Gc = G[base + j];
        float Gs = G[base + DENC + j];
        float cA = eA[base + j];
        float sA = eA[base + DENC + j];
        float den = cA * cA + sA * sA;
        float r  = (Gc * cA + Gs * sA) / den;
        float ii = (Gs * cA - Gc * sA) / den;
        re[q] = r; im[q] = ii;
        acc += r * r + ii * ii;
    }
    red[t] = acc;
    __syncthreads();
#pragma unroll
    for (int s = 128; s > 0; s >>= 1) {
        if (t < s) red[t] += red[t + s];
        __syncthreads();
    }
    float scale = 22.62741699796952f / sqrtf(red[0]);   // sqrt(512)/nrm
#pragma unroll
    for (int q = 0; q < 2; q++) {
        int j = t + q * 256;
        G[base + j]        = re[q] * scale;
        G[base + DENC + j] = im[q] * scale;
    }
}

// ---------------------------------------------------------------------------
extern "C" void kernel_launch(void* const* d_in, const int* in_sizes, int n_in,
                              void* d_out, int out_size)
{
    const float* pts = (const float*)d_in[0];   // 65536 x 3
    const float* A   = (const float*)d_in[1];   // 3 x 512
    const float* B   = (const float*)d_in[2];   // 3 x 4096
    float* out = (float*)d_out;                 // 65536 x 1024 fp32

    float *eA, *eB, *C1;
    cudaGetSymbolAddress((void**)&eA, g_eA);
    cudaGetSymbolAddress((void**)&eB, g_eB);
    cudaGetSymbolAddress((void**)&C1, g_C1);

    const int T = 256;

    // encode: eA (N x 1024), eB (N x 8192), both n-major
    encode_cols<<<((long long)NPTS * DENC) / T, T>>>(pts, A, eA, DENC, 9);
    encode_cols<<<((long long)NPTS * PDIM) / T, T>>>(pts, B, eB, PDIM, 12);

    dim3 blk(256);

    // GEMM1 (TN): C1[p][d] = sum_n eB[n][p] * eA[n][d]     (K = 65536)
    dim3 g1(TWO_D / BN, TWO_P / BM);    // (8, 64)
    gemm_tn<<<g1, blk>>>(eB, eA, C1, NPTS, TWO_P, TWO_D, TWO_D);

    // GEMM2 (NN): G[n][d] = sum_p eB[n][p] * C1[p][d]      (K = 8192)
    dim3 g2(TWO_D / BN, NPTS / BM);     // (8, 512)
    gemm_nn<<<g2, blk>>>(eB, C1, out, TWO_P, TWO_P, TWO_D, TWO_D);

    // re/im + row-norm + scale, in place on d_out
    finalize_kernel<<<NPTS, 256>>>(out, eA);
}

// round 8
// speedup vs baseline: 2.1244x; 2.1244x over previous
#include <cuda_runtime.h>
#include <cuda_bf16.h>
#include <math.h>
#include <stdint.h>

#define NPTS  65536
#define DENC  512
#define PDIM  4096
#define TWO_D 1024
#define TWO_P 8192

typedef unsigned long long u64;
typedef __nv_bfloat16 bf16;

// Scratch (allocation-free __device__ globals, 2.54 GB total — links OK)
__device__ bf16  g_eBh [(u64)NPTS * TWO_P];   // 1 GB   eB hi   [n][8192]
__device__ bf16  g_eBl [(u64)NPTS * TWO_P];   // 1 GB   eB lo
__device__ bf16  g_eATh[(u64)TWO_D * NPTS];   // 128 MB eA^T hi [d][65536]
__device__ bf16  g_eATl[(u64)TWO_D * NPTS];   // 128 MB
__device__ float g_eAf [(u64)NPTS * TWO_D];   // 256 MB eA fp32 [n][1024] (demod)
__device__ bf16  g_C1Th[(u64)TWO_D * TWO_P];  // 16 MB  C1^T hi [d][8192]
__device__ bf16  g_C1Tl[(u64)TWO_D * TWO_P];  // 16 MB

// ---------------- PTX helpers (base sm_103 ISA only) ----------------
__device__ __forceinline__ uint32_t smem_u32(const void* p) {
    uint32_t a;
    asm("{ .reg .u64 t; cvta.to.shared.u64 t, %1; cvt.u32.u64 %0, t; }" : "=r"(a) : "l"(p));
    return a;
}
__device__ __forceinline__ void cp_async16(uint32_t dst, const void* src) {
    asm volatile("cp.async.cg.shared.global [%0], [%1], 16;" :: "r"(dst), "l"(src));
}
#define CP_COMMIT() asm volatile("cp.async.commit_group;" ::: "memory")
#define CP_WAIT1()  asm volatile("cp.async.wait_group 1;" ::: "memory")

__device__ __forceinline__ void ldm_x4(uint32_t* r, uint32_t a) {
    asm volatile("ldmatrix.sync.aligned.m8n8.x4.shared.b16 {%0,%1,%2,%3}, [%4];"
        : "=r"(r[0]), "=r"(r[1]), "=r"(r[2]), "=r"(r[3]) : "r"(a));
}
__device__ __forceinline__ void ldm_x2(uint32_t* r, uint32_t a) {
    asm volatile("ldmatrix.sync.aligned.m8n8.x2.shared.b16 {%0,%1}, [%2];"
        : "=r"(r[0]), "=r"(r[1]) : "r"(a));
}
__device__ __forceinline__ void ldm_x2t(uint32_t* r, uint32_t a) {
    asm volatile("ldmatrix.sync.aligned.m8n8.x2.trans.shared.b16 {%0,%1}, [%2];"
        : "=r"(r[0]), "=r"(r[1]) : "r"(a));
}
__device__ __forceinline__ void mma16816(float* c, const uint32_t* a, const uint32_t* b) {
    asm volatile("mma.sync.aligned.m16n8k16.row.col.f32.bf16.bf16.f32 "
        "{%0,%1,%2,%3}, {%4,%5,%6,%7}, {%8,%9}, {%0,%1,%2,%3};"
        : "+f"(c[0]), "+f"(c[1]), "+f"(c[2]), "+f"(c[3])
        : "r"(a[0]), "r"(a[1]), "r"(a[2]), "r"(a[3]), "r"(b[0]), "r"(b[1]));
}

// ---------------- encode ----------------
__device__ __forceinline__ void split_bf16(float v, bf16& h, bf16& l) {
    h = __float2bfloat16(v);
    l = __float2bfloat16(v - __bfloat162float(h));
}

__global__ void enc_eB(const float* __restrict__ pts, const float* __restrict__ W) {
    u64 idx = (u64)blockIdx.x * 256 + threadIdx.x;
    int p = (int)(idx & 4095);
    int n = (int)(idx >> 12);
    float x0 = pts[3*n+0]*20.f, x1 = pts[3*n+1]*20.f, x2 = pts[3*n+2]*20.f;
    float ph = x0*W[p] + x1*W[PDIM+p] + x2*W[2*PDIM+p];
    float s, c; sincosf(ph, &s, &c);
    bf16 ch, cl, sh, sl;
    split_bf16(c, ch, cl); split_bf16(s, sh, sl);
    u64 b = (u64)n * TWO_P;
    g_eBh[b + p] = ch;        g_eBl[b + p] = cl;
    g_eBh[b + PDIM + p] = sh; g_eBl[b + PDIM + p] = sl;
}

__global__ void enc_eAT(const float* __restrict__ pts, const float* __restrict__ W) {
    u64 idx = (u64)blockIdx.x * 256 + threadIdx.x;
    int n = (int)(idx & 65535);
    int j = (int)(idx >> 16);        // 0..511
    float x0 = pts[3*n+0]*20.f, x1 = pts[3*n+1]*20.f, x2 = pts[3*n+2]*20.f;
    float ph = x0*W[j] + x1*W[DENC+j] + x2*W[2*DENC+j];
    float s, c; sincosf(ph, &s, &c);
    bf16 ch, cl, sh, sl;
    split_bf16(c, ch, cl); split_bf16(s, sh, sl);
    g_eATh[(u64)j * NPTS + n] = ch;          g_eATl[(u64)j * NPTS + n] = cl;
    g_eATh[(u64)(j+DENC) * NPTS + n] = sh;   g_eATl[(u64)(j+DENC) * NPTS + n] = sl;
}

__global__ void enc_eAf(const float* __restrict__ pts, const float* __restrict__ W) {
    u64 idx = (u64)blockIdx.x * 256 + threadIdx.x;
    int j = (int)(idx & 511);
    int n = (int)(idx >> 9);
    float x0 = pts[3*n+0]*20.f, x1 = pts[3*n+1]*20.f, x2 = pts[3*n+2]*20.f;
    float ph = x0*W[j] + x1*W[DENC+j] + x2*W[2*DENC+j];
    float s, c; sincosf(ph, &s, &c);
    u64 b = (u64)n * TWO_D;
    g_eAf[b + j] = c;
    g_eAf[b + DENC + j] = s;
}

// ---------------- mma.sync split-bf16 GEMM ----------------
// D[m][q] = sum_k A[m][k]*B[q][k], 3 bf16 terms (AhBh + AhBl + AlBh), fp32 acc.
// BM=BN=128, BK=32. 8 warps as 2x4 grid, 64x32 warp tiles, m16n8k16 HMMA.
// MODE 1 (GEMM1): A=eAT[d][n] (lda 65536), B=eB[n][p] natural n-major rows
//                 -> B tile stored [k-rows=32][p=128], ldmatrix.x2.trans.
//                 out = C1T bf16 hi/lo [d][p].
// MODE 2 (GEMM2): A=eB[n][p] (lda 8192), B=C1T[d][p] K-contig, ldmatrix.x2.
//                 out = fp32 G [n][d].
// SMEM per stage: Ah@0, Al@10240 (128x40bf16 pad rows), Bh@20480, Bl@+BT_B.
template<int MODE>
__global__ __launch_bounds__(256, 1)
void gemm_mma(const bf16* __restrict__ Agh, const bf16* __restrict__ Agl,
              const bf16* __restrict__ Bgh, const bf16* __restrict__ Bgl,
              float* __restrict__ outF, bf16* __restrict__ outH, bf16* __restrict__ outL)
{
    constexpr int  NK  = (MODE == 1) ? (NPTS / 32) : (TWO_P / 32);
    constexpr u64  LDA = (MODE == 1) ? (u64)NPTS : (u64)TWO_P;
    constexpr int  BT_B = (MODE == 1) ? 32 * 272 : 128 * 80;  // bytes per B tile
    constexpr int  STG  = 20480 + 2 * BT_B;                    // bytes per stage

    extern __shared__ __align__(16) char smem[];
    const uint32_t s0 = smem_u32(smem);

    const int tid  = threadIdx.x;
    const int lane = tid & 31;
    const int wid  = tid >> 5;
    const int wr   = wid >> 2;        // 0..1  (m)
    const int wc   = wid & 3;         // 0..3  (n)

    const int m0 = blockIdx.y * 128;
    const int n0 = blockIdx.x * 128;

    const bf16* Ah = Agh + (u64)m0 * LDA;
    const bf16* Al = Agl + (u64)m0 * LDA;
    const bf16* Bh = (MODE == 1) ? (Bgh + n0) : (Bgh + (u64)n0 * TWO_P);
    const bf16* Bl = (MODE == 1) ? (Bgl + n0) : (Bgl + (u64)n0 * TWO_P);

    // ---- stage loader (lambda-free, inlined twice) ----
#define LOAD_STAGE(SB, KT)                                                     \
    {                                                                          \
        _Pragma("unroll")                                                      \
        for (int p_ = 0; p_ < 2; p_++) {   /* A: 512 chunks of 16B */          \
            int q = tid + p_ * 256;                                            \
            int r = q >> 2, c = q & 3;                                         \
            u64 g = (u64)r * LDA + (u64)(KT) * 32 + c * 8;                     \
            uint32_t d = (SB) + r * 80 + c * 16;                               \
            cp_async16(d,         Ah + g);                                     \
            cp_async16(d + 10240, Al + g);                                     \
        }                                                                      \
        if (MODE == 1) {                   /* B: 32 rows x 256B, n-major */    \
            _Pragma("unroll")                                                  \
            for (int p_ = 0; p_ < 2; p_++) {                                   \
                int q = tid + p_ * 256;                                        \
                int r = q >> 4, c = q & 15;                                    \
                u64 g = (u64)((KT) * 32 + r) * TWO_P + c * 8;                  \
                uint32_t d = (SB) + 20480 + r * 272 + c * 16;                  \
                cp_async16(d,        Bh + g);                                  \
                cp_async16(d + 8704, Bl + g);                                  \
            }                                                                  \
        } else {                           /* B: 128 rows x 64B, K-contig */   \
            _Pragma("unroll")                                                  \
            for (int p_ = 0; p_ < 2; p_++) {                                   \
                int q = tid + p_ * 256;                                        \
                int r = q >> 2, c = q & 3;                                     \
                u64 g = (u64)r * TWO_P + (u64)(KT) * 32 + c * 8;               \
                uint32_t d = (SB) + 20480 + r * 80 + c * 16;                   \
                cp_async16(d,         Bh + g);                                 \
                cp_async16(d + 10240, Bl + g);                                 \
            }                                                                  \
        }                                                                      \
    }

    // per-lane ldmatrix offsets
    const uint32_t aoff  = ((lane & 15) + wr * 64) * 80 + (lane >> 4) * 16;
    const uint32_t boff2 = ((lane & 7) + wc * 32) * 80 + ((lane >> 3) & 1) * 16;
    const uint32_t boff1 = (lane & 15) * 272 + wc * 64;

    float acc[4][4][4];
#pragma unroll
    for (int i = 0; i < 4; i++)
#pragma unroll
        for (int j = 0; j < 4; j++)
#pragma unroll
            for (int k = 0; k < 4; k++) acc[i][j][k] = 0.f;

    LOAD_STAGE(s0, 0);
    CP_COMMIT();

    for (int kt = 0; kt < NK; kt++) {
        if (kt + 1 < NK) LOAD_STAGE(s0 + ((kt + 1) & 1) * STG, kt + 1);
        CP_COMMIT();
        CP_WAIT1();
        __syncthreads();

        const uint32_t Ab = s0 + (kt & 1) * STG;
        const uint32_t Bb = Ab + 20480;

#pragma unroll
        for (int k0 = 0; k0 < 32; k0 += 16) {
            uint32_t ah[4][4], al[4][4], bh[4][2], bl[4][2];
#pragma unroll
            for (int mi = 0; mi < 4; mi++) {
                ldm_x4(ah[mi], Ab + aoff + mi * 1280 + k0 * 2);
                ldm_x4(al[mi], Ab + 10240 + aoff + mi * 1280 + k0 * 2);
            }
#pragma unroll
            for (int ni = 0; ni < 4; ni++) {
                if (MODE == 1) {
                    ldm_x2t(bh[ni], Bb + boff1 + ni * 16 + k0 * 272);
                    ldm_x2t(bl[ni], Bb + 8704 + boff1 + ni * 16 + k0 * 272);
                } else {
                    ldm_x2(bh[ni], Bb + boff2 + ni * 640 + k0 * 2);
                    ldm_x2(bl[ni], Bb + 10240 + boff2 + ni * 640 + k0 * 2);
                }
            }
#pragma unroll
            for (int mi = 0; mi < 4; mi++)
#pragma unroll
                for (int ni = 0; ni < 4; ni++) {
                    mma16816(acc[mi][ni], ah[mi], bh[ni]);   // hi*hi
                    mma16816(acc[mi][ni], ah[mi], bl[ni]);   // hi*lo
                    mma16816(acc[mi][ni], al[mi], bh[ni]);   // lo*hi
                }
        }
        __syncthreads();
    }

    // ---- epilogue ----
    const int rbase = wr * 64 + (lane >> 2);
    const int cbase = wc * 32 + (lane & 3) * 2;
    if (MODE == 1) {
        bf16* oh = outH + (u64)m0 * TWO_P + n0;
        bf16* ol = outL + (u64)m0 * TWO_P + n0;
#pragma unroll
        for (int mi = 0; mi < 4; mi++)
#pragma unroll
            for (int ni = 0; ni < 4; ni++)
#pragma unroll
                for (int hh = 0; hh < 2; hh++) {
                    int r = rbase + mi * 16 + hh * 8;
                    int c = cbase + ni * 8;
                    u64 o = (u64)r * TWO_P + c;
                    float v0 = acc[mi][ni][hh * 2 + 0];
                    float v1 = acc[mi][ni][hh * 2 + 1];
                    bf16 h0, l0, h1, l1;
                    split_bf16(v0, h0, l0);
                    split_bf16(v1, h1, l1);
                    *(__nv_bfloat162*)&oh[o] = __nv_bfloat162(h0, h1);
                    *(__nv_bfloat162*)&ol[o] = __nv_bfloat162(l0, l1);
                }
    } else {
        float* og = outF + (u64)m0 * TWO_D + n0;
#pragma unroll
        for (int mi = 0; mi < 4; mi++)
#pragma unroll
            for (int ni = 0; ni < 4; ni++)
#pragma unroll
                for (int hh = 0; hh < 2; hh++) {
                    int r = rbase + mi * 16 + hh * 8;
                    int c = cbase + ni * 8;
                    *(float2*)&og[(u64)r * TWO_D + c] =
                        make_float2(acc[mi][ni][hh * 2 + 0], acc[mi][ni][hh * 2 + 1]);
                }
    }
#undef LOAD_STAGE
}

// ---------------- finalize ----------------
__global__ void finalize_kernel(float* __restrict__ G, const float* __restrict__ eA)
{
    __shared__ float red[256];
    int n = blockIdx.x, t = threadIdx.x;
    u64 base = (u64)n * TWO_D;
    float re[2], im[2], acc = 0.f;
#pragma unroll
    for (int q = 0; q < 2; q++) {
        int j = t + q * 256;
        float Gc = G[base + j], Gs = G[base + DENC + j];
        float cA = eA[base + j], sA = eA[base + DENC + j];
        float den = cA * cA + sA * sA;
        float r  = (Gc * cA + Gs * sA) / den;
        float ii = (Gs * cA - Gc * sA) / den;
        re[q] = r; im[q] = ii;
        acc += r * r + ii * ii;
    }
    red[t] = acc;
    __syncthreads();
#pragma unroll
    for (int s = 128; s > 0; s >>= 1) {
        if (t < s) red[t] += red[t + s];
        __syncthreads();
    }
    float scale = 22.62741699796952f / sqrtf(red[0]);   // sqrt(512)/nrm
#pragma unroll
    for (int q = 0; q < 2; q++) {
        int j = t + q * 256;
        G[base + j]        = re[q] * scale;
        G[base + DENC + j] = im[q] * scale;
    }
}

// ---------------------------------------------------------------------------
extern "C" void kernel_launch(void* const* d_in, const int* in_sizes, int n_in,
                              void* d_out, int out_size)
{
    const float* pts = (const float*)d_in[0];
    const float* A   = (const float*)d_in[1];
    const float* B   = (const float*)d_in[2];
    float* out = (float*)d_out;

    bf16 *eBh, *eBl, *eATh, *eATl, *C1Th, *C1Tl;
    float *eAf;
    cudaGetSymbolAddress((void**)&eBh,  g_eBh);
    cudaGetSymbolAddress((void**)&eBl,  g_eBl);
    cudaGetSymbolAddress((void**)&eATh, g_eATh);
    cudaGetSymbolAddress((void**)&eATl, g_eATl);
    cudaGetSymbolAddress((void**)&eAf,  g_eAf);
    cudaGetSymbolAddress((void**)&C1Th, g_C1Th);
    cudaGetSymbolAddress((void**)&C1Tl, g_C1Tl);

    const int SMEM1 = 2 * (20480 + 2 * 32 * 272);    // 75776
    const int SMEM2 = 2 * (20480 + 2 * 128 * 80);    // 81920
    cudaFuncSetAttribute(gemm_mma<1>, cudaFuncAttributeMaxDynamicSharedMemorySize, SMEM1);
    cudaFuncSetAttribute(gemm_mma<2>, cudaFuncAttributeMaxDynamicSharedMemorySize, SMEM2);

    enc_eB <<<((u64)NPTS * PDIM) / 256, 256>>>(pts, B);
    enc_eAT<<<((u64)DENC * NPTS) / 256, 256>>>(pts, A);
    enc_eAf<<<((u64)NPTS * DENC) / 256, 256>>>(pts, A);

    // GEMM1: C1T[d][p] = sum_n eAT[d][n] * eB[n][p]   (B via ldmatrix.trans)
    gemm_mma<1><<<dim3(TWO_P / 128, TWO_D / 128), 256, SMEM1>>>(
        eATh, eATl, eBh, eBl, nullptr, C1Th, C1Tl);

    // GEMM2: G[n][d] = sum_p eB[n][p] * C1T[d][p]     (both K-contiguous)
    gemm_mma<2><<<dim3(TWO_D / 128, NPTS / 128), 256, SMEM2>>>(
        eBh, eBl, C1Th, C1Tl, out, nullptr, nullptr);

    finalize_kernel<<<NPTS, 256>>>(out, eAf);
}

// round 9
// speedup vs baseline: 2.1493x; 1.0117x over previous
#include <cuda_runtime.h>
#include <cuda_bf16.h>
#include <math.h>
#include <stdint.h>

#define NPTS  65536
#define DENC  512
#define PDIM  4096
#define TWO_D 1024
#define TWO_P 8192

typedef unsigned long long u64;
typedef __nv_bfloat16 bf16;

// Scratch (allocation-free __device__ globals, 2.54 GB total — links OK)
__device__ bf16  g_eBh [(u64)NPTS * TWO_P];   // 1 GB   eB hi   [n][8192]
__device__ bf16  g_eBl [(u64)NPTS * TWO_P];   // 1 GB   eB lo
__device__ bf16  g_eATh[(u64)TWO_D * NPTS];   // 128 MB eA^T hi [d][65536]
__device__ bf16  g_eATl[(u64)TWO_D * NPTS];   // 128 MB
__device__ float g_eAf [(u64)NPTS * TWO_D];   // 256 MB eA fp32 [n][1024] (demod)
__device__ bf16  g_C1Th[(u64)TWO_D * TWO_P];  // 16 MB  C1^T hi [d][8192]
__device__ bf16  g_C1Tl[(u64)TWO_D * TWO_P];  // 16 MB

// ---------------- PTX helpers (base sm_103 ISA only) ----------------
__device__ __forceinline__ uint32_t smem_u32(const void* p) {
    uint32_t a;
    asm("{ .reg .u64 t; cvta.to.shared.u64 t, %1; cvt.u32.u64 %0, t; }" : "=r"(a) : "l"(p));
    return a;
}
__device__ __forceinline__ void cp_async16(uint32_t dst, const void* src) {
    asm volatile("cp.async.cg.shared.global [%0], [%1], 16;" :: "r"(dst), "l"(src));
}
#define CP_COMMIT() asm volatile("cp.async.commit_group;" ::: "memory")
#define CP_WAIT2()  asm volatile("cp.async.wait_group 2;" ::: "memory")

__device__ __forceinline__ void ldm_x4(uint32_t* r, uint32_t a) {
    asm volatile("ldmatrix.sync.aligned.m8n8.x4.shared.b16 {%0,%1,%2,%3}, [%4];"
        : "=r"(r[0]), "=r"(r[1]), "=r"(r[2]), "=r"(r[3]) : "r"(a));
}
__device__ __forceinline__ void ldm_x2(uint32_t* r, uint32_t a) {
    asm volatile("ldmatrix.sync.aligned.m8n8.x2.shared.b16 {%0,%1}, [%2];"
        : "=r"(r[0]), "=r"(r[1]) : "r"(a));
}
__device__ __forceinline__ void ldm_x2t(uint32_t* r, uint32_t a) {
    asm volatile("ldmatrix.sync.aligned.m8n8.x2.trans.shared.b16 {%0,%1}, [%2];"
        : "=r"(r[0]), "=r"(r[1]) : "r"(a));
}
__device__ __forceinline__ void mma16816(float* c, const uint32_t* a, const uint32_t* b) {
    asm volatile("mma.sync.aligned.m16n8k16.row.col.f32.bf16.bf16.f32 "
        "{%0,%1,%2,%3}, {%4,%5,%6,%7}, {%8,%9}, {%0,%1,%2,%3};"
        : "+f"(c[0]), "+f"(c[1]), "+f"(c[2]), "+f"(c[3])
        : "r"(a[0]), "r"(a[1]), "r"(a[2]), "r"(a[3]), "r"(b[0]), "r"(b[1]));
}

// ---------------- encode ----------------
__device__ __forceinline__ void split_bf16(float v, bf16& h, bf16& l) {
    h = __float2bfloat16(v);
    l = __float2bfloat16(v - __bfloat162float(h));
}

__global__ void enc_eB(const float* __restrict__ pts, const float* __restrict__ W) {
    u64 idx = (u64)blockIdx.x * 256 + threadIdx.x;
    int p = (int)(idx & 4095);
    int n = (int)(idx >> 12);
    float x0 = pts[3*n+0]*20.f, x1 = pts[3*n+1]*20.f, x2 = pts[3*n+2]*20.f;
    float ph = x0*W[p] + x1*W[PDIM+p] + x2*W[2*PDIM+p];
    float s, c; sincosf(ph, &s, &c);
    bf16 ch, cl, sh, sl;
    split_bf16(c, ch, cl); split_bf16(s, sh, sl);
    u64 b = (u64)n * TWO_P;
    g_eBh[b + p] = ch;        g_eBl[b + p] = cl;
    g_eBh[b + PDIM + p] = sh; g_eBl[b + PDIM + p] = sl;
}

__global__ void enc_eAT(const float* __restrict__ pts, const float* __restrict__ W) {
    u64 idx = (u64)blockIdx.x * 256 + threadIdx.x;
    int n = (int)(idx & 65535);
    int j = (int)(idx >> 16);        // 0..511
    float x0 = pts[3*n+0]*20.f, x1 = pts[3*n+1]*20.f, x2 = pts[3*n+2]*20.f;
    float ph = x0*W[j] + x1*W[DENC+j] + x2*W[2*DENC+j];
    float s, c; sincosf(ph, &s, &c);
    bf16 ch, cl, sh, sl;
    split_bf16(c, ch, cl); split_bf16(s, sl = sl, sl);  // placeholder avoided below
    // (redo cleanly)
    split_bf16(c, ch, cl); split_bf16(s, sh, sl);
    g_eATh[(u64)j * NPTS + n] = ch;          g_eATl[(u64)j * NPTS + n] = cl;
    g_eATh[(u64)(j+DENC) * NPTS + n] = sh;   g_eATl[(u64)(j+DENC) * NPTS + n] = sl;
}

__global__ void enc_eAf(const float* __restrict__ pts, const float* __restrict__ W) {
    u64 idx = (u64)blockIdx.x * 256 + threadIdx.x;
    int j = (int)(idx & 511);
    int n = (int)(idx >> 9);
    float x0 = pts[3*n+0]*20.f, x1 = pts[3*n+1]*20.f, x2 = pts[3*n+2]*20.f;
    float ph = x0*W[j] + x1*W[DENC+j] + x2*W[2*DENC+j];
    float s, c; sincosf(ph, &s, &c);
    u64 b = (u64)n * TWO_D;
    g_eAf[b + j] = c;
    g_eAf[b + DENC + j] = s;
}

// ---------------- mma.sync split-bf16 GEMM, 4-stage pipeline ----------------
// D[m][q] = sum_k A[m][k]*B[q][k], 3 bf16 terms (AhBh + AhBl + AlBh), fp32 acc.
// BM=BN=128, BK=32. 8 warps as 2x4 grid, 64x32 warp tiles, m16n8k16 HMMA.
// MODE 1 (GEMM1): A=eAT[d][n], B=eB[n][p] n-major -> ldmatrix.x2.trans.
// MODE 2 (GEMM2): A=eB[n][p],  B=C1T[d][p] K-contig -> ldmatrix.x2.
// Mainloop: wait_group(2) -> one __syncthreads -> prefetch stage kt+3 ->
// commit (always; empty groups at tail keep the retirement invariant) ->
// compute stage kt%4.
template<int MODE>
__global__ __launch_bounds__(256, 1)
void gemm_mma(const bf16* __restrict__ Agh, const bf16* __restrict__ Agl,
              const bf16* __restrict__ Bgh, const bf16* __restrict__ Bgl,
              float* __restrict__ outF, bf16* __restrict__ outH, bf16* __restrict__ outL)
{
    constexpr int  NK   = (MODE == 1) ? (NPTS / 32) : (TWO_P / 32);
    constexpr u64  LDA  = (MODE == 1) ? (u64)NPTS : (u64)TWO_P;
    constexpr int  BT_B = (MODE == 1) ? 32 * 272 : 128 * 80;   // bytes per B tile (hi)
    constexpr int  STG  = 20480 + 2 * BT_B;                    // bytes per stage

    extern __shared__ __align__(16) char smem[];
    const uint32_t s0 = smem_u32(smem);

    const int tid  = threadIdx.x;
    const int lane = tid & 31;
    const int wid  = tid >> 5;
    const int wr   = wid >> 2;        // 0..1  (m)
    const int wc   = wid & 3;         // 0..3  (n)

    const int m0 = blockIdx.y * 128;
    const int n0 = blockIdx.x * 128;

    const bf16* Ah = Agh + (u64)m0 * LDA;
    const bf16* Al = Agl + (u64)m0 * LDA;
    const bf16* Bh = (MODE == 1) ? (Bgh + n0) : (Bgh + (u64)n0 * TWO_P);
    const bf16* Bl = (MODE == 1) ? (Bgl + n0) : (Bgl + (u64)n0 * TWO_P);

#define LOAD_STAGE(SB, KT)                                                     \
    {                                                                          \
        _Pragma("unroll")                                                      \
        for (int p_ = 0; p_ < 2; p_++) {   /* A: 512 chunks of 16B */          \
            int q = tid + p_ * 256;                                            \
            int r = q >> 2, c = q & 3;                                         \
            u64 g = (u64)r * LDA + (u64)(KT) * 32 + c * 8;                     \
            uint32_t d = (SB) + r * 80 + c * 16;                               \
            cp_async16(d,         Ah + g);                                     \
            cp_async16(d + 10240, Al + g);                                     \
        }                                                                      \
        if (MODE == 1) {                   /* B: 32 rows x 256B, n-major */    \
            _Pragma("unroll")                                                  \
            for (int p_ = 0; p_ < 2; p_++) {                                   \
                int q = tid + p_ * 256;                                        \
                int r = q >> 4, c = q & 15;                                    \
                u64 g = (u64)((KT) * 32 + r) * TWO_P + c * 8;                  \
                uint32_t d = (SB) + 20480 + r * 272 + c * 16;                  \
                cp_async16(d,        Bh + g);                                  \
                cp_async16(d + 8704, Bl + g);                                  \
            }                                                                  \
        } else {                           /* B: 128 rows x 64B, K-contig */   \
            _Pragma("unroll")                                                  \
            for (int p_ = 0; p_ < 2; p_++) {                                   \
                int q = tid + p_ * 256;                                        \
                int r = q >> 2, c = q & 3;                                     \
                u64 g = (u64)r * TWO_P + (u64)(KT) * 32 + c * 8;               \
                uint32_t d = (SB) + 20480 + r * 80 + c * 16;                   \
                cp_async16(d,         Bh + g);                                 \
                cp_async16(d + 10240, Bl + g);                                 \
            }                                                                  \
        }                                                                      \
    }

    // per-lane ldmatrix offsets (unchanged from validated R8 kernel)
    const uint32_t aoff  = ((lane & 15) + wr * 64) * 80 + (lane >> 4) * 16;
    const uint32_t boff2 = ((lane & 7) + wc * 32) * 80 + ((lane >> 3) & 1) * 16;
    const uint32_t boff1 = (lane & 15) * 272 + wc * 64;

    float acc[4][4][4];
#pragma unroll
    for (int i = 0; i < 4; i++)
#pragma unroll
        for (int j = 0; j < 4; j++)
#pragma unroll
            for (int k = 0; k < 4; k++) acc[i][j][k] = 0.f;

    // prologue: stages 0,1,2 in flight (groups 0,1,2)
    LOAD_STAGE(s0 + 0 * STG, 0); CP_COMMIT();
    LOAD_STAGE(s0 + 1 * STG, 1); CP_COMMIT();
    LOAD_STAGE(s0 + 2 * STG, 2); CP_COMMIT();

    for (int kt = 0; kt < NK; kt++) {
        CP_WAIT2();                    // groups <= kt retired -> stage kt landed
        __syncthreads();               // all warps done with stage (kt+3)%4 reads

        if (kt + 3 < NK) LOAD_STAGE(s0 + ((kt + 3) & 3) * STG, kt + 3);
        CP_COMMIT();                   // always: keeps group<->stage numbering

        const uint32_t Ab = s0 + (kt & 3) * STG;
        const uint32_t Bb = Ab + 20480;

#pragma unroll
        for (int k0 = 0; k0 < 32; k0 += 16) {
            uint32_t ah[4][4], al[4][4], bh[4][2], bl[4][2];
#pragma unroll
            for (int mi = 0; mi < 4; mi++) {
                ldm_x4(ah[mi], Ab + aoff + mi * 1280 + k0 * 2);
                ldm_x4(al[mi], Ab + 10240 + aoff + mi * 1280 + k0 * 2);
            }
#pragma unroll
            for (int ni = 0; ni < 4; ni++) {
                if (MODE == 1) {
                    ldm_x2t(bh[ni], Bb + boff1 + ni * 16 + k0 * 272);
                    ldm_x2t(bl[ni], Bb + 8704 + boff1 + ni * 16 + k0 * 272);
                } else {
                    ldm_x2(bh[ni], Bb + boff2 + ni * 640 + k0 * 2);
                    ldm_x2(bl[ni], Bb + 10240 + boff2 + ni * 640 + k0 * 2);
                }
            }
#pragma unroll
            for (int mi = 0; mi < 4; mi++)
#pragma unroll
                for (int ni = 0; ni < 4; ni++) {
                    mma16816(acc[mi][ni], ah[mi], bh[ni]);   // hi*hi
                    mma16816(acc[mi][ni], ah[mi], bl[ni]);   // hi*lo
                    mma16816(acc[mi][ni], al[mi], bh[ni]);   // lo*hi
                }
        }
    }

    // ---- epilogue ----
    const int rbase = wr * 64 + (lane >> 2);
    const int cbase = wc * 32 + (lane & 3) * 2;
    if (MODE == 1) {
        bf16* oh = outH + (u64)m0 * TWO_P + n0;
        bf16* ol = outL + (u64)m0 * TWO_P + n0;
#pragma unroll
        for (int mi = 0; mi < 4; mi++)
#pragma unroll
            for (int ni = 0; ni < 4; ni++)
#pragma unroll
                for (int hh = 0; hh < 2; hh++) {
                    int r = rbase + mi * 16 + hh * 8;
                    int c = cbase + ni * 8;
                    u64 o = (u64)r * TWO_P + c;
                    float v0 = acc[mi][ni][hh * 2 + 0];
                    float v1 = acc[mi][ni][hh * 2 + 1];
                    bf16 h0, l0, h1, l1;
                    split_bf16(v0, h0, l0);
                    split_bf16(v1, h1, l1);
                    *(__nv_bfloat162*)&oh[o] = __nv_bfloat162(h0, h1);
                    *(__nv_bfloat162*)&ol[o] = __nv_bfloat162(l0, l1);
                }
    } else {
        float* og = outF + (u64)m0 * TWO_D + n0;
#pragma unroll
        for (int mi = 0; mi < 4; mi++)
#pragma unroll
            for (int ni = 0; ni < 4; ni++)
#pragma unroll
                for (int hh = 0; hh < 2; hh++) {
                    int r = rbase + mi * 16 + hh * 8;
                    int c = cbase + ni * 8;
                    *(float2*)&og[(u64)r * TWO_D + c] =
                        make_float2(acc[mi][ni][hh * 2 + 0], acc[mi][ni][hh * 2 + 1]);
                }
    }
#undef LOAD_STAGE
}

// ---------------- finalize ----------------
__global__ void finalize_kernel(float* __restrict__ G, const float* __restrict__ eA)
{
    __shared__ float red[256];
    int n = blockIdx.x, t = threadIdx.x;
    u64 base = (u64)n * TWO_D;
    float re[2], im[2], acc = 0.f;
#pragma unroll
    for (int q = 0; q < 2; q++) {
        int j = t + q * 256;
        float Gc = G[base + j], Gs = G[base + DENC + j];
        float cA = eA[base + j], sA = eA[base + DENC + j];
        float den = cA * cA + sA * sA;
        float r  = (Gc * cA + Gs * sA) / den;
        float ii = (Gs * cA - Gc * sA) / den;
        re[q] = r; im[q] = ii;
        acc += r * r + ii * ii;
    }
    red[t] = acc;
    __syncthreads();
#pragma unroll
    for (int s = 128; s > 0; s >>= 1) {
        if (t < s) red[t] += red[t + s];
        __syncthreads();
    }
    float scale = 22.62741699796952f / sqrtf(red[0]);   // sqrt(512)/nrm
#pragma unroll
    for (int q = 0; q < 2; q++) {
        int j = t + q * 256;
        G[base + j]        = re[q] * scale;
        G[base + DENC + j] = im[q] * scale;
    }
}

// ---------------------------------------------------------------------------
extern "C" void kernel_launch(void* const* d_in, const int* in_sizes, int n_in,
                              void* d_out, int out_size)
{
    const float* pts = (const float*)d_in[0];
    const float* A   = (const float*)d_in[1];
    const float* B   = (const float*)d_in[2];
    float* out = (float*)d_out;

    bf16 *eBh, *eBl, *eATh, *eATl, *C1Th, *C1Tl;
    float *eAf;
    cudaGetSymbolAddress((void**)&eBh,  g_eBh);
    cudaGetSymbolAddress((void**)&eBl,  g_eBl);
    cudaGetSymbolAddress((void**)&eATh, g_eATh);
    cudaGetSymbolAddress((void**)&eATl, g_eATl);
    cudaGetSymbolAddress((void**)&eAf,  g_eAf);
    cudaGetSymbolAddress((void**)&C1Th, g_C1Th);
    cudaGetSymbolAddress((void**)&C1Tl, g_C1Tl);

    const int SMEM1 = 4 * (20480 + 2 * 32 * 272);    // 151552
    const int SMEM2 = 4 * (20480 + 2 * 128 * 80);    // 163840
    cudaFuncSetAttribute(gemm_mma<1>, cudaFuncAttributeMaxDynamicSharedMemorySize, SMEM1);
    cudaFuncSetAttribute(gemm_mma<2>, cudaFuncAttributeMaxDynamicSharedMemorySize, SMEM2);

    enc_eB <<<((u64)NPTS * PDIM) / 256, 256>>>(pts, B);
    enc_eAT<<<((u64)DENC * NPTS) / 256, 256>>>(pts, A);
    enc_eAf<<<((u64)NPTS * DENC) / 256, 256>>>(pts, A);

    // GEMM1: C1T[d][p] = sum_n eAT[d][n] * eB[n][p]   (B via ldmatrix.trans)
    gemm_mma<1><<<dim3(TWO_P / 128, TWO_D / 128), 256, SMEM1>>>(
        eATh, eATl, eBh, eBl, nullptr, C1Th, C1Tl);

    // GEMM2: G[n][d] = sum_p eB[n][p] * C1T[d][p]     (both K-contiguous)
    gemm_mma<2><<<dim3(TWO_D / 128, NPTS / 128), 256, SMEM2>>>(
        eBh, eBl, C1Th, C1Tl, out, nullptr, nullptr);

    finalize_kernel<<<NPTS, 256>>>(out, eAf);
}

// round 10
// speedup vs baseline: 3.0742x; 1.4303x over previous
#include <cuda_runtime.h>
#include <cuda_bf16.h>
#include <math.h>
#include <stdint.h>

#define NPTS  65536
#define DENC  512
#define PDIM  4096
#define TWO_D 1024
#define TWO_P 8192

typedef unsigned long long u64;
typedef __nv_bfloat16 bf16;

// Scratch (allocation-free __device__ globals, 2.54 GB total — links OK)
__device__ bf16  g_eBh [(u64)NPTS * TWO_P];   // 1 GB   eB hi   [n][8192]
__device__ bf16  g_eBl [(u64)NPTS * TWO_P];   // 1 GB   eB lo
__device__ bf16  g_eATh[(u64)TWO_D * NPTS];   // 128 MB eA^T hi [d][65536]
__device__ bf16  g_eATl[(u64)TWO_D * NPTS];   // 128 MB
__device__ float g_eAf [(u64)NPTS * TWO_D];   // 256 MB eA fp32 [n][1024] (demod)
__device__ bf16  g_C1Th[(u64)TWO_D * TWO_P];  // 16 MB  C1^T hi [d][8192]
__device__ bf16  g_C1Tl[(u64)TWO_D * TWO_P];  // 16 MB

// ---------------- PTX helpers (base sm_103 ISA only) ----------------
__device__ __forceinline__ uint32_t smem_u32(const void* p) {
    uint32_t a;
    asm("{ .reg .u64 t; cvta.to.shared.u64 t, %1; cvt.u32.u64 %0, t; }" : "=r"(a) : "l"(p));
    return a;
}
__device__ __forceinline__ void cp_async16(uint32_t dst, const void* src) {
    asm volatile("cp.async.cg.shared.global [%0], [%1], 16;" :: "r"(dst), "l"(src));
}
#define CP_COMMIT() asm volatile("cp.async.commit_group;" ::: "memory")
#define CP_WAIT3()  asm volatile("cp.async.wait_group 3;" ::: "memory")
#define CP_WAIT2()  asm volatile("cp.async.wait_group 2;" ::: "memory")

__device__ __forceinline__ void ldm_x4(uint32_t* r, uint32_t a) {
    asm volatile("ldmatrix.sync.aligned.m8n8.x4.shared.b16 {%0,%1,%2,%3}, [%4];"
        : "=r"(r[0]), "=r"(r[1]), "=r"(r[2]), "=r"(r[3]) : "r"(a));
}
__device__ __forceinline__ void ldm_x2(uint32_t* r, uint32_t a) {
    asm volatile("ldmatrix.sync.aligned.m8n8.x2.shared.b16 {%0,%1}, [%2];"
        : "=r"(r[0]), "=r"(r[1]) : "r"(a));
}
__device__ __forceinline__ void ldm_x2t(uint32_t* r, uint32_t a) {
    asm volatile("ldmatrix.sync.aligned.m8n8.x2.trans.shared.b16 {%0,%1}, [%2];"
        : "=r"(r[0]), "=r"(r[1]) : "r"(a));
}
__device__ __forceinline__ void mma16816(float* c, const uint32_t* a, const uint32_t* b) {
    asm volatile("mma.sync.aligned.m16n8k16.row.col.f32.bf16.bf16.f32 "
        "{%0,%1,%2,%3}, {%4,%5,%6,%7}, {%8,%9}, {%0,%1,%2,%3};"
        : "+f"(c[0]), "+f"(c[1]), "+f"(c[2]), "+f"(c[3])
        : "r"(a[0]), "r"(a[1]), "r"(a[2]), "r"(a[3]), "r"(b[0]), "r"(b[1]));
}

// ---------------- encode ----------------
__device__ __forceinline__ void split_bf16(float v, bf16& h, bf16& l) {
    h = __float2bfloat16(v);
    l = __float2bfloat16(v - __bfloat162float(h));
}

__global__ void enc_eB(const float* __restrict__ pts, const float* __restrict__ W) {
    u64 idx = (u64)blockIdx.x * 256 + threadIdx.x;
    int p = (int)(idx & 4095);
    int n = (int)(idx >> 12);
    float x0 = pts[3*n+0]*20.f, x1 = pts[3*n+1]*20.f, x2 = pts[3*n+2]*20.f;
    float ph = x0*W[p] + x1*W[PDIM+p] + x2*W[2*PDIM+p];
    float s, c; __sincosf(ph, &s, &c);     // fast path: phase err ~1e-5 grade
    bf16 ch, cl, sh, sl;
    split_bf16(c, ch, cl); split_bf16(s, sh, sl);
    u64 b = (u64)n * TWO_P;
    g_eBh[b + p] = ch;        g_eBl[b + p] = cl;
    g_eBh[b + PDIM + p] = sh; g_eBl[b + PDIM + p] = sl;
}

__global__ void enc_eAT(const float* __restrict__ pts, const float* __restrict__ W) {
    u64 idx = (u64)blockIdx.x * 256 + threadIdx.x;
    int n = (int)(idx & 65535);
    int j = (int)(idx >> 16);        // 0..511
    float x0 = pts[3*n+0]*20.f, x1 = pts[3*n+1]*20.f, x2 = pts[3*n+2]*20.f;
    float ph = x0*W[j] + x1*W[DENC+j] + x2*W[2*DENC+j];
    float s, c; sincosf(ph, &s, &c);
    bf16 ch, cl, sh, sl;
    split_bf16(c, ch, cl); split_bf16(s, sh, sl);
    g_eATh[(u64)j * NPTS + n] = ch;          g_eATl[(u64)j * NPTS + n] = cl;
    g_eATh[(u64)(j+DENC) * NPTS + n] = sh;   g_eATl[(u64)(j+DENC) * NPTS + n] = sl;
}

__global__ void enc_eAf(const float* __restrict__ pts, const float* __restrict__ W) {
    u64 idx = (u64)blockIdx.x * 256 + threadIdx.x;
    int j = (int)(idx & 511);
    int n = (int)(idx >> 9);
    float x0 = pts[3*n+0]*20.f, x1 = pts[3*n+1]*20.f, x2 = pts[3*n+2]*20.f;
    float ph = x0*W[j] + x1*W[DENC+j] + x2*W[2*DENC+j];
    float s, c; sincosf(ph, &s, &c);
    u64 b = (u64)n * TWO_D;
    g_eAf[b + j] = c;
    g_eAf[b + DENC + j] = s;
}

// ---------------- mma.sync split-bf16 GEMM, frag-pipelined ----------------
// D[m][q] = sum_k A[m][k]*B[q][k], 3 bf16 terms (AhBh + AhBl + AlBh), fp32 acc.
// BM=BN=128, BK=32, 5-stage cp.async ring, register fragments double-buffered:
// LDSM for step t+1 issues before the HMMAs of step t (LSU || tensor overlap).
// HMMA terms ordered term-outer so consecutive HMMAs never RAW one accumulator.
template<int MODE>
__global__ __launch_bounds__(256, 1)
void gemm_mma(const bf16* __restrict__ Agh, const bf16* __restrict__ Agl,
              const bf16* __restrict__ Bgh, const bf16* __restrict__ Bgl,
              float* __restrict__ outF, bf16* __restrict__ outH, bf16* __restrict__ outL)
{
    constexpr int  NK   = (MODE == 1) ? (NPTS / 32) : (TWO_P / 32);
    constexpr u64  LDA  = (MODE == 1) ? (u64)NPTS : (u64)TWO_P;
    constexpr int  BT_B = (MODE == 1) ? 32 * 272 : 128 * 80;   // bytes per B tile (hi)
    constexpr int  STG  = 20480 + 2 * BT_B;                    // bytes per stage

    extern __shared__ __align__(16) char smem[];
    const uint32_t s0 = smem_u32(smem);

    const int tid  = threadIdx.x;
    const int lane = tid & 31;
    const int wid  = tid >> 5;
    const int wr   = wid >> 2;        // 0..1  (m)
    const int wc   = wid & 3;         // 0..3  (n)

    const int m0 = blockIdx.y * 128;
    const int n0 = blockIdx.x * 128;

    const bf16* Ah = Agh + (u64)m0 * LDA;
    const bf16* Al = Agl + (u64)m0 * LDA;
    const bf16* Bh = (MODE == 1) ? (Bgh + n0) : (Bgh + (u64)n0 * TWO_P);
    const bf16* Bl = (MODE == 1) ? (Bgl + n0) : (Bgl + (u64)n0 * TWO_P);

#define LOAD_STAGE(SB, KT)                                                     \
    {                                                                          \
        _Pragma("unroll")                                                      \
        for (int p_ = 0; p_ < 2; p_++) {   /* A: 512 chunks of 16B */          \
            int q = tid + p_ * 256;                                            \
            int r = q >> 2, c = q & 3;                                         \
            u64 g = (u64)r * LDA + (u64)(KT) * 32 + c * 8;                     \
            uint32_t d = (SB) + r * 80 + c * 16;                               \
            cp_async16(d,         Ah + g);                                     \
            cp_async16(d + 10240, Al + g);                                     \
        }                                                                      \
        if (MODE == 1) {                   /* B: 32 rows x 256B, n-major */    \
            _Pragma("unroll")                                                  \
            for (int p_ = 0; p_ < 2; p_++) {                                   \
                int q = tid + p_ * 256;                                        \
                int r = q >> 4, c = q & 15;                                    \
                u64 g = (u64)((KT) * 32 + r) * TWO_P + c * 8;                  \
                uint32_t d = (SB) + 20480 + r * 272 + c * 16;                  \
                cp_async16(d,        Bh + g);                                  \
                cp_async16(d + 8704, Bl + g);                                  \
            }                                                                  \
        } else {                           /* B: 128 rows x 64B, K-contig */   \
            _Pragma("unroll")                                                  \
            for (int p_ = 0; p_ < 2; p_++) {                                   \
                int q = tid + p_ * 256;                                        \
                int r = q >> 2, c = q & 3;                                     \
                u64 g = (u64)r * TWO_P + (u64)(KT) * 32 + c * 8;               \
                uint32_t d = (SB) + 20480 + r * 80 + c * 16;                   \
                cp_async16(d,         Bh + g);                                 \
                cp_async16(d + 10240, Bl + g);                                 \
            }                                                                  \
        }                                                                      \
    }

    // per-lane ldmatrix offsets (validated in R8)
    const uint32_t aoff  = ((lane & 15) + wr * 64) * 80 + (lane >> 4) * 16;
    const uint32_t boff2 = ((lane & 7) + wc * 32) * 80 + ((lane >> 3) & 1) * 16;
    const uint32_t boff1 = (lane & 15) * 272 + wc * 64;

#define LDFRAGS(AH, AL, BH, BL, AB, K0)                                        \
    {                                                                          \
        uint32_t Bb_ = (AB) + 20480;                                           \
        _Pragma("unroll")                                                      \
        for (int mi = 0; mi < 4; mi++) {                                       \
            ldm_x4(AH[mi], (AB) + aoff + mi * 1280 + (K0) * 2);                \
            ldm_x4(AL[mi], (AB) + 10240 + aoff + mi * 1280 + (K0) * 2);        \
        }                                                                      \
        _Pragma("unroll")                                                      \
        for (int ni = 0; ni < 4; ni++) {                                       \
            if (MODE == 1) {                                                   \
                ldm_x2t(BH[ni], Bb_ + boff1 + ni * 16 + (K0) * 272);           \
                ldm_x2t(BL[ni], Bb_ + 8704 + boff1 + ni * 16 + (K0) * 272);    \
            } else {                                                           \
                ldm_x2(BH[ni], Bb_ + boff2 + ni * 640 + (K0) * 2);             \
                ldm_x2(BL[ni], Bb_ + 10240 + boff2 + ni * 640 + (K0) * 2);     \
            }                                                                  \
        }                                                                      \
    }

#define DO_HMMA(AH, AL, BH, BL)                                                \
    {                                                                          \
        _Pragma("unroll")                                                      \
        for (int mi = 0; mi < 4; mi++)                                         \
        _Pragma("unroll")                                                      \
        for (int ni = 0; ni < 4; ni++) mma16816(acc[mi][ni], AH[mi], BH[ni]);  \
        _Pragma("unroll")                                                      \
        for (int mi = 0; mi < 4; mi++)                                         \
        _Pragma("unroll")                                                      \
        for (int ni = 0; ni < 4; ni++) mma16816(acc[mi][ni], AH[mi], BL[ni]);  \
        _Pragma("unroll")                                                      \
        for (int mi = 0; mi < 4; mi++)                                         \
        _Pragma("unroll")                                                      \
        for (int ni = 0; ni < 4; ni++) mma16816(acc[mi][ni], AL[mi], BH[ni]);  \
    }

    float acc[4][4][4];
#pragma unroll
    for (int i = 0; i < 4; i++)
#pragma unroll
        for (int j = 0; j < 4; j++)
#pragma unroll
            for (int k = 0; k < 4; k++) acc[i][j][k] = 0.f;

    uint32_t ah0[4][4], al0[4][4], bh0[4][2], bl0[4][2];
    uint32_t ah1[4][4], al1[4][4], bh1[4][2], bl1[4][2];

    // prologue: stages 0..3 in flight
    LOAD_STAGE(s0 + 0 * STG, 0); CP_COMMIT();
    LOAD_STAGE(s0 + 1 * STG, 1); CP_COMMIT();
    LOAD_STAGE(s0 + 2 * STG, 2); CP_COMMIT();
    LOAD_STAGE(s0 + 3 * STG, 3); CP_COMMIT();
    CP_WAIT3();                      // stage 0 landed
    __syncthreads();
    LDFRAGS(ah0, al0, bh0, bl0, s0, 0);          // frags(chunk 0, k0=0)

    int scur = 0;                    // stage ring index of chunk kt
    for (int kt = 0; kt < NK; kt++) {
        const uint32_t Ab = s0 + scur * STG;
        int snxt = scur + 1; if (snxt == 5) snxt = 0;
        const uint32_t Abn = s0 + snxt * STG;
        int spre = (scur == 0) ? 4 : scur - 1;   // (kt+4) % 5

        LDFRAGS(ah1, al1, bh1, bl1, Ab, 16);     // LSU: frags(kt, k0=16)
        DO_HMMA(ah0, al0, bh0, bl0);             // tensor: frags(kt, k0=0)

        CP_WAIT2();                              // stage kt+1 landed
        __syncthreads();                         // all warps past stage spre reads
        if (kt + 4 < NK) LOAD_STAGE(s0 + spre * STG, kt + 4);
        CP_COMMIT();                             // always: group numbering invariant

        if (kt + 1 < NK) LDFRAGS(ah0, al0, bh0, bl0, Abn, 0);  // frags(kt+1, 0)
        DO_HMMA(ah1, al1, bh1, bl1);             // frags(kt, k0=16)

        scur = snxt;
    }

    // ---- epilogue ----
    const int rbase = wr * 64 + (lane >> 2);
    const int cbase = wc * 32 + (lane & 3) * 2;
    if (MODE == 1) {
        bf16* oh = outH + (u64)m0 * TWO_P + n0;
        bf16* ol = outL + (u64)m0 * TWO_P + n0;
#pragma unroll
        for (int mi = 0; mi < 4; mi++)
#pragma unroll
            for (int ni = 0; ni < 4; ni++)
#pragma unroll
                for (int hh = 0; hh < 2; hh++) {
                    int r = rbase + mi * 16 + hh * 8;
                    int c = cbase + ni * 8;
                    u64 o = (u64)r * TWO_P + c;
                    float v0 = acc[mi][ni][hh * 2 + 0];
                    float v1 = acc[mi][ni][hh * 2 + 1];
                    bf16 h0, l0, h1, l1;
                    split_bf16(v0, h0, l0);
                    split_bf16(v1, h1, l1);
                    *(__nv_bfloat162*)&oh[o] = __nv_bfloat162(h0, h1);
                    *(__nv_bfloat162*)&ol[o] = __nv_bfloat162(l0, l1);
                }
    } else {
        float* og = outF + (u64)m0 * TWO_D + n0;
#pragma unroll
        for (int mi = 0; mi < 4; mi++)
#pragma unroll
            for (int ni = 0; ni < 4; ni++)
#pragma unroll
                for (int hh = 0; hh < 2; hh++) {
                    int r = rbase + mi * 16 + hh * 8;
                    int c = cbase + ni * 8;
                    *(float2*)&og[(u64)r * TWO_D + c] =
                        make_float2(acc[mi][ni][hh * 2 + 0], acc[mi][ni][hh * 2 + 1]);
                }
    }
#undef LOAD_STAGE
#undef LDFRAGS
#undef DO_HMMA
}

// ---------------- finalize ----------------
__global__ void finalize_kernel(float* __restrict__ G, const float* __restrict__ eA)
{
    __shared__ float red[256];
    int n = blockIdx.x, t = threadIdx.x;
    u64 base = (u64)n * TWO_D;
    float re[2], im[2], acc = 0.f;
#pragma unroll
    for (int q = 0; q < 2; q++) {
        int j = t + q * 256;
        float Gc = G[base + j], Gs = G[base + DENC + j];
        float cA = eA[base + j], sA = eA[base + DENC + j];
        float den = cA * cA + sA * sA;
        float r  = (Gc * cA + Gs * sA) / den;
        float ii = (Gs * cA - Gc * sA) / den;
        re[q] = r; im[q] = ii;
        acc += r * r + ii * ii;
    }
    red[t] = acc;
    __syncthreads();
#pragma unroll
    for (int s = 128; s > 0; s >>= 1) {
        if (t < s) red[t] += red[t + s];
        __syncthreads();
    }
    float scale = 22.62741699796952f / sqrtf(red[0]);   // sqrt(512)/nrm
#pragma unroll
    for (int q = 0; q < 2; q++) {
        int j = t + q * 256;
        G[base + j]        = re[q] * scale;
        G[base + DENC + j] = im[q] * scale;
    }
}

// ---------------------------------------------------------------------------
extern "C" void kernel_launch(void* const* d_in, const int* in_sizes, int n_in,
                              void* d_out, int out_size)
{
    const float* pts = (const float*)d_in[0];
    const float* A   = (const float*)d_in[1];
    const float* B   = (const float*)d_in[2];
    float* out = (float*)d_out;

    bf16 *eBh, *eBl, *eATh, *eATl, *C1Th, *C1Tl;
    float *eAf;
    cudaGetSymbolAddress((void**)&eBh,  g_eBh);
    cudaGetSymbolAddress((void**)&eBl,  g_eBl);
    cudaGetSymbolAddress((void**)&eATh, g_eATh);
    cudaGetSymbolAddress((void**)&eATl, g_eATl);
    cudaGetSymbolAddress((void**)&eAf,  g_eAf);
    cudaGetSymbolAddress((void**)&C1Th, g_C1Th);
    cudaGetSymbolAddress((void**)&C1Tl, g_C1Tl);

    const int SMEM1 = 5 * (20480 + 2 * 32 * 272);    // 189440
    const int SMEM2 = 5 * (20480 + 2 * 128 * 80);    // 204800
    cudaFuncSetAttribute(gemm_mma<1>, cudaFuncAttributeMaxDynamicSharedMemorySize, SMEM1);
    cudaFuncSetAttribute(gemm_mma<2>, cudaFuncAttributeMaxDynamicSharedMemorySize, SMEM2);

    enc_eB <<<((u64)NPTS * PDIM) / 256, 256>>>(pts, B);
    enc_eAT<<<((u64)DENC * NPTS) / 256, 256>>>(pts, A);
    enc_eAf<<<((u64)NPTS * DENC) / 256, 256>>>(pts, A);

    // GEMM1: C1T[d][p] = sum_n eAT[d][n] * eB[n][p]   (B via ldmatrix.trans)
    gemm_mma<1><<<dim3(TWO_P / 128, TWO_D / 128), 256, SMEM1>>>(
        eATh, eATl, eBh, eBl, nullptr, C1Th, C1Tl);

    // GEMM2: G[n][d] = sum_p eB[n][p] * C1T[d][p]     (both K-contiguous)
    gemm_mma<2><<<dim3(TWO_D / 128, NPTS / 128), 256, SMEM2>>>(
        eBh, eBl, C1Th, C1Tl, out, nullptr, nullptr);

    finalize_kernel<<<NPTS, 256>>>(out, eAf);
}

// round 11
// speedup vs baseline: 3.1660x; 1.0299x over previous
#include <cuda_runtime.h>
#include <cuda_bf16.h>
#include <math.h>
#include <stdint.h>

#define NPTS  65536
#define DENC  512
#define PDIM  4096
#define TWO_D 1024
#define TWO_P 8192

typedef unsigned long long u64;
typedef __nv_bfloat16 bf16;

// Scratch (allocation-free __device__ globals, ~2.3 GB total — links OK)
__device__ bf16  g_eBh [(u64)NPTS * TWO_P];   // 1 GB   eB hi   [n][8192]
__device__ bf16  g_eBl [(u64)NPTS * TWO_P];   // 1 GB   eB lo
__device__ bf16  g_eATh[(u64)TWO_D * NPTS];   // 128 MB eA^T hi [d][65536]
__device__ bf16  g_eATl[(u64)TWO_D * NPTS];   // 128 MB
__device__ bf16  g_C1Th[(u64)TWO_D * TWO_P];  // 16 MB  C1^T hi [d][8192]
__device__ bf16  g_C1Tl[(u64)TWO_D * TWO_P];  // 16 MB

// ---------------- PTX helpers (base sm_103 ISA only) ----------------
__device__ __forceinline__ uint32_t smem_u32(const void* p) {
    uint32_t a;
    asm("{ .reg .u64 t; cvta.to.shared.u64 t, %1; cvt.u32.u64 %0, t; }" : "=r"(a) : "l"(p));
    return a;
}
__device__ __forceinline__ void cp_async16(uint32_t dst, const void* src) {
    asm volatile("cp.async.cg.shared.global [%0], [%1], 16;" :: "r"(dst), "l"(src));
}
#define CP_COMMIT() asm volatile("cp.async.commit_group;" ::: "memory")
#define CP_WAIT3()  asm volatile("cp.async.wait_group 3;" ::: "memory")
#define CP_WAIT2()  asm volatile("cp.async.wait_group 2;" ::: "memory")

__device__ __forceinline__ void ldm_x4(uint32_t* r, uint32_t a) {
    asm volatile("ldmatrix.sync.aligned.m8n8.x4.shared.b16 {%0,%1,%2,%3}, [%4];"
        : "=r"(r[0]), "=r"(r[1]), "=r"(r[2]), "=r"(r[3]) : "r"(a));
}
__device__ __forceinline__ void ldm_x4t(uint32_t* r, uint32_t a) {
    asm volatile("ldmatrix.sync.aligned.m8n8.x4.trans.shared.b16 {%0,%1,%2,%3}, [%4];"
        : "=r"(r[0]), "=r"(r[1]), "=r"(r[2]), "=r"(r[3]) : "r"(a));
}
__device__ __forceinline__ void mma16816(float* c, const uint32_t* a, const uint32_t* b) {
    asm volatile("mma.sync.aligned.m16n8k16.row.col.f32.bf16.bf16.f32 "
        "{%0,%1,%2,%3}, {%4,%5,%6,%7}, {%8,%9}, {%0,%1,%2,%3};"
        : "+f"(c[0]), "+f"(c[1]), "+f"(c[2]), "+f"(c[3])
        : "r"(a[0]), "r"(a[1]), "r"(a[2]), "r"(a[3]), "r"(b[0]), "r"(b[1]));
}

// ---------------- encode ----------------
__device__ __forceinline__ void split_bf16(float v, bf16& h, bf16& l) {
    h = __float2bfloat16(v);
    l = __float2bfloat16(v - __bfloat162float(h));
}

__global__ void enc_eB(const float* __restrict__ pts, const float* __restrict__ W) {
    u64 idx = (u64)blockIdx.x * 256 + threadIdx.x;
    int p = (int)(idx & 4095);
    int n = (int)(idx >> 12);
    float x0 = pts[3*n+0]*20.f, x1 = pts[3*n+1]*20.f, x2 = pts[3*n+2]*20.f;
    float ph = x0*W[p] + x1*W[PDIM+p] + x2*W[2*PDIM+p];
    float s, c; __sincosf(ph, &s, &c);     // fast path: phase err ~1e-5 grade
    bf16 ch, cl, sh, sl;
    split_bf16(c, ch, cl); split_bf16(s, sh, sl);
    u64 b = (u64)n * TWO_P;
    g_eBh[b + p] = ch;        g_eBl[b + p] = cl;
    g_eBh[b + PDIM + p] = sh; g_eBl[b + PDIM + p] = sl;
}

__global__ void enc_eAT(const float* __restrict__ pts, const float* __restrict__ W) {
    u64 idx = (u64)blockIdx.x * 256 + threadIdx.x;
    int n = (int)(idx & 65535);
    int j = (int)(idx >> 16);        // 0..511
    float x0 = pts[3*n+0]*20.f, x1 = pts[3*n+1]*20.f, x2 = pts[3*n+2]*20.f;
    float ph = x0*W[j] + x1*W[DENC+j] + x2*W[2*DENC+j];
    float s, c; sincosf(ph, &s, &c);
    bf16 ch, cl, sh, sl;
    split_bf16(c, ch, cl); split_bf16(s, sh, sl);
    g_eATh[(u64)j * NPTS + n] = ch;          g_eATl[(u64)j * NPTS + n] = cl;
    g_eATh[(u64)(j+DENC) * NPTS + n] = sh;   g_eATl[(u64)(j+DENC) * NPTS + n] = sl;
}

// ---------------- mma.sync split-bf16 GEMM, frag-pipelined ----------------
// D[m][q] = sum_k A[m][k]*B[q][k], 3 bf16 terms (AhBh + AhBl + AlBh), fp32 acc.
// BM=BN=128, BK=32, 5-stage cp.async ring, register fragments double-buffered.
// B fragments loaded with fused ldmatrix.x4 (2 n-frags per instruction).
template<int MODE>
__global__ __launch_bounds__(256, 1)
void gemm_mma(const bf16* __restrict__ Agh, const bf16* __restrict__ Agl,
              const bf16* __restrict__ Bgh, const bf16* __restrict__ Bgl,
              float* __restrict__ outF, bf16* __restrict__ outH, bf16* __restrict__ outL)
{
    constexpr int  NK   = (MODE == 1) ? (NPTS / 32) : (TWO_P / 32);
    constexpr u64  LDA  = (MODE == 1) ? (u64)NPTS : (u64)TWO_P;
    constexpr int  BT_B = (MODE == 1) ? 32 * 272 : 128 * 80;   // bytes per B tile (hi)
    constexpr int  STG  = 20480 + 2 * BT_B;                    // bytes per stage

    extern __shared__ __align__(16) char smem[];
    const uint32_t s0 = smem_u32(smem);

    const int tid  = threadIdx.x;
    const int lane = tid & 31;
    const int wid  = tid >> 5;
    const int wr   = wid >> 2;        // 0..1  (m)
    const int wc   = wid & 3;         // 0..3  (n)

    const int m0 = blockIdx.y * 128;
    const int n0 = blockIdx.x * 128;

    const bf16* Ah = Agh + (u64)m0 * LDA;
    const bf16* Al = Agl + (u64)m0 * LDA;
    const bf16* Bh = (MODE == 1) ? (Bgh + n0) : (Bgh + (u64)n0 * TWO_P);
    const bf16* Bl = (MODE == 1) ? (Bgl + n0) : (Bgl + (u64)n0 * TWO_P);

#define LOAD_STAGE(SB, KT)                                                     \
    {                                                                          \
        _Pragma("unroll")                                                      \
        for (int p_ = 0; p_ < 2; p_++) {   /* A: 512 chunks of 16B */          \
            int q = tid + p_ * 256;                                            \
            int r = q >> 2, c = q & 3;                                         \
            u64 g = (u64)r * LDA + (u64)(KT) * 32 + c * 8;                     \
            uint32_t d = (SB) + r * 80 + c * 16;                               \
            cp_async16(d,         Ah + g);                                     \
            cp_async16(d + 10240, Al + g);                                     \
        }                                                                      \
        if (MODE == 1) {                   /* B: 32 rows x 256B, n-major */    \
            _Pragma("unroll")                                                  \
            for (int p_ = 0; p_ < 2; p_++) {                                   \
                int q = tid + p_ * 256;                                        \
                int r = q >> 4, c = q & 15;                                    \
                u64 g = (u64)((KT) * 32 + r) * TWO_P + c * 8;                  \
                uint32_t d = (SB) + 20480 + r * 272 + c * 16;                  \
                cp_async16(d,        Bh + g);                                  \
                cp_async16(d + 8704, Bl + g);                                  \
            }                                                                  \
        } else {                           /* B: 128 rows x 64B, K-contig */   \
            _Pragma("unroll")                                                  \
            for (int p_ = 0; p_ < 2; p_++) {                                   \
                int q = tid + p_ * 256;                                        \
                int r = q >> 2, c = q & 3;                                     \
                u64 g = (u64)r * TWO_P + (u64)(KT) * 32 + c * 8;               \
                uint32_t d = (SB) + 20480 + r * 80 + c * 16;                   \
                cp_async16(d,         Bh + g);                                 \
                cp_async16(d + 10240, Bl + g);                                 \
            }                                                                  \
        }                                                                      \
    }

    // per-lane ldmatrix offsets
    const uint32_t aoff = ((lane & 15) + wr * 64) * 80 + (lane >> 4) * 16;
    // MODE2 fused-x4 B: lanes16-31 address the +8-row (next n-frag) matrices
    const uint32_t boff2x = ((lane & 7) + ((lane >> 4) & 1) * 8 + wc * 32) * 80
                          + ((lane >> 3) & 1) * 16;
    // MODE1 fused-x4 trans B: lanes16-31 address the +16B (next n-frag) cols
    const uint32_t boff1x = (lane & 15) * 272 + wc * 64 + ((lane >> 4) & 1) * 16;

#define LDFRAGS(AH, AL, BH, BL, AB, K0)                                        \
    {                                                                          \
        uint32_t Bb_ = (AB) + 20480;                                           \
        _Pragma("unroll")                                                      \
        for (int mi = 0; mi < 4; mi++) {                                       \
            ldm_x4(AH[mi], (AB) + aoff + mi * 1280 + (K0) * 2);                \
            ldm_x4(AL[mi], (AB) + 10240 + aoff + mi * 1280 + (K0) * 2);        \
        }                                                                      \
        _Pragma("unroll")                                                      \
        for (int ni = 0; ni < 4; ni += 2) {                                    \
            if (MODE == 1) {                                                   \
                ldm_x4t(&BH[ni][0], Bb_ + boff1x + ni * 16 + (K0) * 272);      \
                ldm_x4t(&BL[ni][0], Bb_ + 8704 + boff1x + ni * 16 + (K0) * 272);\
            } else {                                                           \
                ldm_x4(&BH[ni][0], Bb_ + boff2x + ni * 640 + (K0) * 2);        \
                ldm_x4(&BL[ni][0], Bb_ + 10240 + boff2x + ni * 640 + (K0) * 2);\
            }                                                                  \
        }                                                                      \
    }

#define DO_HMMA(AH, AL, BH, BL)                                                \
    {                                                                          \
        _Pragma("unroll")                                                      \
        for (int mi = 0; mi < 4; mi++)                                         \
        _Pragma("unroll")                                                      \
        for (int ni = 0; ni < 4; ni++) mma16816(acc[mi][ni], AH[mi], BH[ni]);  \
        _Pragma("unroll")                                                      \
        for (int mi = 0; mi < 4; mi++)                                         \
        _Pragma("unroll")                                                      \
        for (int ni = 0; ni < 4; ni++) mma16816(acc[mi][ni], AH[mi], BL[ni]);  \
        _Pragma("unroll")                                                      \
        for (int mi = 0; mi < 4; mi++)                                         \
        _Pragma("unroll")                                                      \
        for (int ni = 0; ni < 4; ni++) mma16816(acc[mi][ni], AL[mi], BH[ni]);  \
    }

    float acc[4][4][4];
#pragma unroll
    for (int i = 0; i < 4; i++)
#pragma unroll
        for (int j = 0; j < 4; j++)
#pragma unroll
            for (int k = 0; k < 4; k++) acc[i][j][k] = 0.f;

    uint32_t ah0[4][4], al0[4][4], bh0[4][2], bl0[4][2];
    uint32_t ah1[4][4], al1[4][4], bh1[4][2], bl1[4][2];

    // prologue: stages 0..3 in flight
    LOAD_STAGE(s0 + 0 * STG, 0); CP_COMMIT();
    LOAD_STAGE(s0 + 1 * STG, 1); CP_COMMIT();
    LOAD_STAGE(s0 + 2 * STG, 2); CP_COMMIT();
    LOAD_STAGE(s0 + 3 * STG, 3); CP_COMMIT();
    CP_WAIT3();                      // stage 0 landed
    __syncthreads();
    LDFRAGS(ah0, al0, bh0, bl0, s0, 0);          // frags(chunk 0, k0=0)

    int scur = 0;                    // stage ring index of chunk kt
    for (int kt = 0; kt < NK; kt++) {
        const uint32_t Ab = s0 + scur * STG;
        int snxt = scur + 1; if (snxt == 5) snxt = 0;
        const uint32_t Abn = s0 + snxt * STG;
        int spre = (scur == 0) ? 4 : scur - 1;   // (kt+4) % 5

        LDFRAGS(ah1, al1, bh1, bl1, Ab, 16);     // LSU: frags(kt, k0=16)
        DO_HMMA(ah0, al0, bh0, bl0);             // tensor: frags(kt, k0=0)

        CP_WAIT2();                              // stage kt+1 landed
        __syncthreads();                         // all warps past stage spre reads
        if (kt + 4 < NK) LOAD_STAGE(s0 + spre * STG, kt + 4);
        CP_COMMIT();                             // always: group numbering invariant

        if (kt + 1 < NK) LDFRAGS(ah0, al0, bh0, bl0, Abn, 0);  // frags(kt+1, 0)
        DO_HMMA(ah1, al1, bh1, bl1);             // frags(kt, k0=16)

        scur = snxt;
    }

    // ---- epilogue ----
    const int rbase = wr * 64 + (lane >> 2);
    const int cbase = wc * 32 + (lane & 3) * 2;
    if (MODE == 1) {
        bf16* oh = outH + (u64)m0 * TWO_P + n0;
        bf16* ol = outL + (u64)m0 * TWO_P + n0;
#pragma unroll
        for (int mi = 0; mi < 4; mi++)
#pragma unroll
            for (int ni = 0; ni < 4; ni++)
#pragma unroll
                for (int hh = 0; hh < 2; hh++) {
                    int r = rbase + mi * 16 + hh * 8;
                    int c = cbase + ni * 8;
                    u64 o = (u64)r * TWO_P + c;
                    float v0 = acc[mi][ni][hh * 2 + 0];
                    float v1 = acc[mi][ni][hh * 2 + 1];
                    bf16 h0, l0, h1, l1;
                    split_bf16(v0, h0, l0);
                    split_bf16(v1, h1, l1);
                    *(__nv_bfloat162*)&oh[o] = __nv_bfloat162(h0, h1);
                    *(__nv_bfloat162*)&ol[o] = __nv_bfloat162(l0, l1);
                }
    } else {
        float* og = outF + (u64)m0 * TWO_D + n0;
#pragma unroll
        for (int mi = 0; mi < 4; mi++)
#pragma unroll
            for (int ni = 0; ni < 4; ni++)
#pragma unroll
                for (int hh = 0; hh < 2; hh++) {
                    int r = rbase + mi * 16 + hh * 8;
                    int c = cbase + ni * 8;
                    *(float2*)&og[(u64)r * TWO_D + c] =
                        make_float2(acc[mi][ni][hh * 2 + 0], acc[mi][ni][hh * 2 + 1]);
                }
    }
#undef LOAD_STAGE
#undef LDFRAGS
#undef DO_HMMA
}

// ---------------- finalize (recomputes eA phases inline) ----------------
__global__ void finalize_kernel(float* __restrict__ G, const float* __restrict__ pts,
                                const float* __restrict__ W)
{
    __shared__ float red[256];
    int n = blockIdx.x, t = threadIdx.x;
    u64 base = (u64)n * TWO_D;
    float x0 = pts[3*n+0]*20.f, x1 = pts[3*n+1]*20.f, x2 = pts[3*n+2]*20.f;

    float re[2], im[2], acc = 0.f;
#pragma unroll
    for (int q = 0; q < 2; q++) {
        int j = t + q * 256;
        float ph = x0*W[j] + x1*W[DENC+j] + x2*W[2*DENC+j];
        float sA, cA; sincosf(ph, &sA, &cA);
        float Gc = G[base + j], Gs = G[base + DENC + j];
        float den = cA * cA + sA * sA;
        float r  = (Gc * cA + Gs * sA) / den;
        float ii = (Gs * cA - Gc * sA) / den;
        re[q] = r; im[q] = ii;
        acc += r * r + ii * ii;
    }
    red[t] = acc;
    __syncthreads();
#pragma unroll
    for (int s = 128; s > 0; s >>= 1) {
        if (t < s) red[t] += red[t + s];
        __syncthreads();
    }
    float scale = 22.62741699796952f / sqrtf(red[0]);   // sqrt(512)/nrm
#pragma unroll
    for (int q = 0; q < 2; q++) {
        int j = t + q * 256;
        G[base + j]        = re[q] * scale;
        G[base + DENC + j] = im[q] * scale;
    }
}

// ---------------------------------------------------------------------------
extern "C" void kernel_launch(void* const* d_in, const int* in_sizes, int n_in,
                              void* d_out, int out_size)
{
    const float* pts = (const float*)d_in[0];
    const float* A   = (const float*)d_in[1];
    const float* B   = (const float*)d_in[2];
    float* out = (float*)d_out;

    bf16 *eBh, *eBl, *eATh, *eATl, *C1Th, *C1Tl;
    cudaGetSymbolAddress((void**)&eBh,  g_eBh);
    cudaGetSymbolAddress((void**)&eBl,  g_eBl);
    cudaGetSymbolAddress((void**)&eATh, g_eATh);
    cudaGetSymbolAddress((void**)&eATl, g_eATl);
    cudaGetSymbolAddress((void**)&C1Th, g_C1Th);
    cudaGetSymbolAddress((void**)&C1Tl, g_C1Tl);

    const int SMEM1 = 5 * (20480 + 2 * 32 * 272);    // 189440
    const int SMEM2 = 5 * (20480 + 2 * 128 * 80);    // 204800
    cudaFuncSetAttribute(gemm_mma<1>, cudaFuncAttributeMaxDynamicSharedMemorySize, SMEM1);
    cudaFuncSetAttribute(gemm_mma<2>, cudaFuncAttributeMaxDynamicSharedMemorySize, SMEM2);

    enc_eB <<<((u64)NPTS * PDIM) / 256, 256>>>(pts, B);
    enc_eAT<<<((u64)DENC * NPTS) / 256, 256>>>(pts, A);

    // GEMM1: C1T[d][p] = sum_n eAT[d][n] * eB[n][p]   (B via fused ldmatrix.x4.trans)
    gemm_mma<1><<<dim3(TWO_P / 128, TWO_D / 128), 256, SMEM1>>>(
        eATh, eATl, eBh, eBl, nullptr, C1Th, C1Tl);

    // GEMM2: G[n][d] = sum_p eB[n][p] * C1T[d][p]     (fused ldmatrix.x4)
    gemm_mma<2><<<dim3(TWO_D / 128, NPTS / 128), 256, SMEM2>>>(
        eBh, eBl, C1Th, C1Tl, out, nullptr, nullptr);

    finalize_kernel<<<NPTS, 256>>>(out, pts, A);
}

// round 12
// speedup vs baseline: 3.3720x; 1.0651x over previous
#include <cuda_runtime.h>
#include <cuda_bf16.h>
#include <math.h>
#include <stdint.h>

#define NPTS  65536
#define DENC  512
#define PDIM  4096
#define TWO_D 1024
#define TWO_P 8192
#define KSPLIT 4

typedef unsigned long long u64;
typedef __nv_bfloat16 bf16;

// Scratch (allocation-free __device__ globals, ~2.42 GB total — links OK)
__device__ bf16  g_eBh [(u64)NPTS * TWO_P];   // 1 GB   eB hi   [n][8192]
__device__ bf16  g_eBl [(u64)NPTS * TWO_P];   // 1 GB   eB lo
__device__ bf16  g_eATh[(u64)TWO_D * NPTS];   // 128 MB eA^T hi [d][65536]
__device__ bf16  g_eATl[(u64)TWO_D * NPTS];   // 128 MB
__device__ bf16  g_C1Th[(u64)TWO_D * TWO_P];  // 16 MB  C1^T hi [d][8192]
__device__ bf16  g_C1Tl[(u64)TWO_D * TWO_P];  // 16 MB
__device__ float g_C1p [(u64)KSPLIT * TWO_D * TWO_P];  // 128 MB split-K partials

// ---------------- PTX helpers (base sm_103 ISA only) ----------------
__device__ __forceinline__ uint32_t smem_u32(const void* p) {
    uint32_t a;
    asm("{ .reg .u64 t; cvta.to.shared.u64 t, %1; cvt.u32.u64 %0, t; }" : "=r"(a) : "l"(p));
    return a;
}
__device__ __forceinline__ void cp_async16(uint32_t dst, const void* src) {
    asm volatile("cp.async.cg.shared.global [%0], [%1], 16;" :: "r"(dst), "l"(src));
}
#define CP_COMMIT() asm volatile("cp.async.commit_group;" ::: "memory")
#define CP_WAIT3()  asm volatile("cp.async.wait_group 3;" ::: "memory")
#define CP_WAIT2()  asm volatile("cp.async.wait_group 2;" ::: "memory")

__device__ __forceinline__ void ldm_x4(uint32_t* r, uint32_t a) {
    asm volatile("ldmatrix.sync.aligned.m8n8.x4.shared.b16 {%0,%1,%2,%3}, [%4];"
        : "=r"(r[0]), "=r"(r[1]), "=r"(r[2]), "=r"(r[3]) : "r"(a));
}
__device__ __forceinline__ void ldm_x4t(uint32_t* r, uint32_t a) {
    asm volatile("ldmatrix.sync.aligned.m8n8.x4.trans.shared.b16 {%0,%1,%2,%3}, [%4];"
        : "=r"(r[0]), "=r"(r[1]), "=r"(r[2]), "=r"(r[3]) : "r"(a));
}
__device__ __forceinline__ void mma16816(float* c, const uint32_t* a, const uint32_t* b) {
    asm volatile("mma.sync.aligned.m16n8k16.row.col.f32.bf16.bf16.f32 "
        "{%0,%1,%2,%3}, {%4,%5,%6,%7}, {%8,%9}, {%0,%1,%2,%3};"
        : "+f"(c[0]), "+f"(c[1]), "+f"(c[2]), "+f"(c[3])
        : "r"(a[0]), "r"(a[1]), "r"(a[2]), "r"(a[3]), "r"(b[0]), "r"(b[1]));
}

// ---------------- fast accurate sincos ----------------
// Cody-Waite 2-term pi/2 reduction + __sinf/__cosf on [-pi/4, pi/4].
// |x| <= ~2000: abs err ~4e-7.
__device__ __forceinline__ void fast_sincos(float x, float& s, float& c) {
    float kf = rintf(x * 0.636619772f);          // 2/pi
    int   q  = (int)kf;
    float r  = fmaf(kf, -1.57079637f, x);        // pi/2 hi (0x3FC90FDB), exact via fma
    r = fmaf(kf, 4.37113900e-8f, r);             // hi - pi/2 correction
    float sr = __sinf(r), cr = __cosf(r);
    bool  sw = q & 1;
    float s0 = sw ? cr : sr;
    float c0 = sw ? sr : cr;
    s = (q & 2) ? -s0 : s0;
    c = ((q + 1) & 2) ? -c0 : c0;
}

// ---------------- encode ----------------
__device__ __forceinline__ void split_bf16(float v, bf16& h, bf16& l) {
    h = __float2bfloat16(v);
    l = __float2bfloat16(v - __bfloat162float(h));
}

__global__ void enc_eB(const float* __restrict__ pts, const float* __restrict__ W) {
    u64 idx = (u64)blockIdx.x * 256 + threadIdx.x;
    int p = (int)(idx & 4095);
    int n = (int)(idx >> 12);
    float x0 = pts[3*n+0]*20.f, x1 = pts[3*n+1]*20.f, x2 = pts[3*n+2]*20.f;
    float ph = x0*W[p] + x1*W[PDIM+p] + x2*W[2*PDIM+p];
    float s, c; fast_sincos(ph, s, c);
    bf16 ch, cl, sh, sl;
    split_bf16(c, ch, cl); split_bf16(s, sh, sl);
    u64 b = (u64)n * TWO_P;
    g_eBh[b + p] = ch;        g_eBl[b + p] = cl;
    g_eBh[b + PDIM + p] = sh; g_eBl[b + PDIM + p] = sl;
}

__global__ void enc_eAT(const float* __restrict__ pts, const float* __restrict__ W) {
    u64 idx = (u64)blockIdx.x * 256 + threadIdx.x;
    int n = (int)(idx & 65535);
    int j = (int)(idx >> 16);        // 0..511
    float x0 = pts[3*n+0]*20.f, x1 = pts[3*n+1]*20.f, x2 = pts[3*n+2]*20.f;
    float ph = x0*W[j] + x1*W[DENC+j] + x2*W[2*DENC+j];
    float s, c; fast_sincos(ph, s, c);
    bf16 ch, cl, sh, sl;
    split_bf16(c, ch, cl); split_bf16(s, sh, sl);
    g_eATh[(u64)j * NPTS + n] = ch;          g_eATl[(u64)j * NPTS + n] = cl;
    g_eATh[(u64)(j+DENC) * NPTS + n] = sh;   g_eATl[(u64)(j+DENC) * NPTS + n] = sl;
}

// ---------------- mma.sync split-bf16 GEMM, frag-pipelined ----------------
// D[m][q] = sum_k A[m][k]*B[q][k], 3 bf16 terms (AhBh + AhBl + AlBh), fp32 acc.
// BM=BN=128, BK=32, 5-stage cp.async ring, register fragments double-buffered.
// MODE 1 (GEMM1): split-K x4 via blockIdx.z, fp32 partials to outF.
// MODE 2 (GEMM2): single K pass, fp32 out.
template<int MODE>
__global__ __launch_bounds__(256, 1)
void gemm_mma(const bf16* __restrict__ Agh, const bf16* __restrict__ Agl,
              const bf16* __restrict__ Bgh, const bf16* __restrict__ Bgl,
              float* __restrict__ outF)
{
    constexpr int  NK   = (MODE == 1) ? (NPTS / KSPLIT / 32) : (TWO_P / 32);
    constexpr u64  LDA  = (MODE == 1) ? (u64)NPTS : (u64)TWO_P;
    constexpr int  BT_B = (MODE == 1) ? 32 * 272 : 128 * 80;   // bytes per B tile (hi)
    constexpr int  STG  = 20480 + 2 * BT_B;                    // bytes per stage

    extern __shared__ __align__(16) char smem[];
    const uint32_t s0 = smem_u32(smem);

    const int tid  = threadIdx.x;
    const int lane = tid & 31;
    const int wid  = tid >> 5;
    const int wr   = wid >> 2;        // 0..1  (m)
    const int wc   = wid & 3;         // 0..3  (n)

    const int m0 = blockIdx.y * 128;
    const int n0 = blockIdx.x * 128;
    const u64 koff = (MODE == 1) ? (u64)blockIdx.z * (NPTS / KSPLIT) : 0;

    const bf16* Ah = Agh + (u64)m0 * LDA + koff;
    const bf16* Al = Agl + (u64)m0 * LDA + koff;
    const bf16* Bh = (MODE == 1) ? (Bgh + n0 + koff * TWO_P) : (Bgh + (u64)n0 * TWO_P);
    const bf16* Bl = (MODE == 1) ? (Bgl + n0 + koff * TWO_P) : (Bgl + (u64)n0 * TWO_P);

#define LOAD_STAGE(SB, KT)                                                     \
    {                                                                          \
        _Pragma("unroll")                                                      \
        for (int p_ = 0; p_ < 2; p_++) {   /* A: 512 chunks of 16B */          \
            int q = tid + p_ * 256;                                            \
            int r = q >> 2, c = q & 3;                                         \
            u64 g = (u64)r * LDA + (u64)(KT) * 32 + c * 8;                     \
            uint32_t d = (SB) + r * 80 + c * 16;                               \
            cp_async16(d,         Ah + g);                                     \
            cp_async16(d + 10240, Al + g);                                     \
        }                                                                      \
        if (MODE == 1) {                   /* B: 32 rows x 256B, n-major */    \
            _Pragma("unroll")                                                  \
            for (int p_ = 0; p_ < 2; p_++) {                                   \
                int q = tid + p_ * 256;                                        \
                int r = q >> 4, c = q & 15;                                    \
                u64 g = (u64)((KT) * 32 + r) * TWO_P + c * 8;                  \
                uint32_t d = (SB) + 20480 + r * 272 + c * 16;                  \
                cp_async16(d,        Bh + g);                                  \
                cp_async16(d + 8704, Bl + g);                                  \
            }                                                                  \
        } else {                           /* B: 128 rows x 64B, K-contig */   \
            _Pragma("unroll")                                                  \
            for (int p_ = 0; p_ < 2; p_++) {                                   \
                int q = tid + p_ * 256;                                        \
                int r = q >> 2, c = q & 3;                                     \
                u64 g = (u64)r * TWO_P + (u64)(KT) * 32 + c * 8;               \
                uint32_t d = (SB) + 20480 + r * 80 + c * 16;                   \
                cp_async16(d,         Bh + g);                                 \
                cp_async16(d + 10240, Bl + g);                                 \
            }                                                                  \
        }                                                                      \
    }

    // per-lane ldmatrix offsets
    const uint32_t aoff = ((lane & 15) + wr * 64) * 80 + (lane >> 4) * 16;
    // MODE2 fused-x4 B: lanes16-31 address the +8-row (next n-frag) matrices
    const uint32_t boff2x = ((lane & 7) + ((lane >> 4) & 1) * 8 + wc * 32) * 80
                          + ((lane >> 3) & 1) * 16;
    // MODE1 fused-x4 trans B: lanes16-31 address the +16B (next n-frag) cols
    const uint32_t boff1x = (lane & 15) * 272 + wc * 64 + ((lane >> 4) & 1) * 16;

#define LDFRAGS(AH, AL, BH, BL, AB, K0)                                        \
    {                                                                          \
        uint32_t Bb_ = (AB) + 20480;                                           \
        _Pragma("unroll")                                                      \
        for (int mi = 0; mi < 4; mi++) {                                       \
            ldm_x4(AH[mi], (AB) + aoff + mi * 1280 + (K0) * 2);                \
            ldm_x4(AL[mi], (AB) + 10240 + aoff + mi * 1280 + (K0) * 2);        \
        }                                                                      \
        _Pragma("unroll")                                                      \
        for (int ni = 0; ni < 4; ni += 2) {                                    \
            if (MODE == 1) {                                                   \
                ldm_x4t(&BH[ni][0], Bb_ + boff1x + ni * 16 + (K0) * 272);      \
                ldm_x4t(&BL[ni][0], Bb_ + 8704 + boff1x + ni * 16 + (K0) * 272);\
            } else {                                                           \
                ldm_x4(&BH[ni][0], Bb_ + boff2x + ni * 640 + (K0) * 2);        \
                ldm_x4(&BL[ni][0], Bb_ + 10240 + boff2x + ni * 640 + (K0) * 2);\
            }                                                                  \
        }                                                                      \
    }

#define DO_HMMA(AH, AL, BH, BL)                                                \
    {                                                                          \
        _Pragma("unroll")                                                      \
        for (int mi = 0; mi < 4; mi++)                                         \
        _Pragma("unroll")                                                      \
        for (int ni = 0; ni < 4; ni++) mma16816(acc[mi][ni], AH[mi], BH[ni]);  \
        _Pragma("unroll")                                                      \
        for (int mi = 0; mi < 4; mi++)                                         \
        _Pragma("unroll")                                                      \
        for (int ni = 0; ni < 4; ni++) mma16816(acc[mi][ni], AH[mi], BL[ni]);  \
        _Pragma("unroll")                                                      \
        for (int mi = 0; mi < 4; mi++)                                         \
        _Pragma("unroll")                                                      \
        for (int ni = 0; ni < 4; ni++) mma16816(acc[mi][ni], AL[mi], BH[ni]);  \
    }

    float acc[4][4][4];
#pragma unroll
    for (int i = 0; i < 4; i++)
#pragma unroll
        for (int j = 0; j < 4; j++)
#pragma unroll
            for (int k = 0; k < 4; k++) acc[i][j][k] = 0.f;

    uint32_t ah0[4][4], al0[4][4], bh0[4][2], bl0[4][2];
    uint32_t ah1[4][4], al1[4][4], bh1[4][2], bl1[4][2];

    // prologue: stages 0..3 in flight
    LOAD_STAGE(s0 + 0 * STG, 0); CP_COMMIT();
    LOAD_STAGE(s0 + 1 * STG, 1); CP_COMMIT();
    LOAD_STAGE(s0 + 2 * STG, 2); CP_COMMIT();
    LOAD_STAGE(s0 + 3 * STG, 3); CP_COMMIT();
    CP_WAIT3();                      // stage 0 landed
    __syncthreads();
    LDFRAGS(ah0, al0, bh0, bl0, s0, 0);          // frags(chunk 0, k0=0)

    int scur = 0;                    // stage ring index of chunk kt
    for (int kt = 0; kt < NK; kt++) {
        const uint32_t Ab = s0 + scur * STG;
        int snxt = scur + 1; if (snxt == 5) snxt = 0;
        const uint32_t Abn = s0 + snxt * STG;
        int spre = (scur == 0) ? 4 : scur - 1;   // (kt+4) % 5

        LDFRAGS(ah1, al1, bh1, bl1, Ab, 16);     // LSU: frags(kt, k0=16)
        DO_HMMA(ah0, al0, bh0, bl0);             // tensor: frags(kt, k0=0)

        CP_WAIT2();                              // stage kt+1 landed
        __syncthreads();                         // all warps past stage spre reads
        if (kt + 4 < NK) LOAD_STAGE(s0 + spre * STG, kt + 4);
        CP_COMMIT();                             // always: group numbering invariant

        if (kt + 1 < NK) LDFRAGS(ah0, al0, bh0, bl0, Abn, 0);  // frags(kt+1, 0)
        DO_HMMA(ah1, al1, bh1, bl1);             // frags(kt, k0=16)

        scur = snxt;
    }

    // ---- epilogue (fp32 out both modes) ----
    const int rbase = wr * 64 + (lane >> 2);
    const int cbase = wc * 32 + (lane & 3) * 2;
    const u64 ldc  = (MODE == 1) ? (u64)TWO_P : (u64)TWO_D;
    float* og = outF + (u64)m0 * ldc + n0
              + ((MODE == 1) ? (u64)blockIdx.z * ((u64)TWO_D * TWO_P) : 0);
#pragma unroll
    for (int mi = 0; mi < 4; mi++)
#pragma unroll
        for (int ni = 0; ni < 4; ni++)
#pragma unroll
            for (int hh = 0; hh < 2; hh++) {
                int r = rbase + mi * 16 + hh * 8;
                int c = cbase + ni * 8;
                *(float2*)&og[(u64)r * ldc + c] =
                    make_float2(acc[mi][ni][hh * 2 + 0], acc[mi][ni][hh * 2 + 1]);
            }
#undef LOAD_STAGE
#undef LDFRAGS
#undef DO_HMMA
}

// ---------------- split-K reduce + bf16 split of C1 ----------------
__global__ void reduce_c1(const float* __restrict__ P,
                          bf16* __restrict__ Th, bf16* __restrict__ Tl)
{
    const u64 CH = (u64)TWO_D * TWO_P;
    u64 i = ((u64)blockIdx.x * 256 + threadIdx.x) * 2;
    float2 a0 = *(const float2*)&P[i];
    float2 a1 = *(const float2*)&P[CH + i];
    float2 a2 = *(const float2*)&P[2 * CH + i];
    float2 a3 = *(const float2*)&P[3 * CH + i];
    float v0 = (a0.x + a1.x) + (a2.x + a3.x);
    float v1 = (a0.y + a1.y) + (a2.y + a3.y);
    bf16 h0, l0, h1, l1;
    split_bf16(v0, h0, l0);
    split_bf16(v1, h1, l1);
    *(__nv_bfloat162*)&Th[i] = __nv_bfloat162(h0, h1);
    *(__nv_bfloat162*)&Tl[i] = __nv_bfloat162(l0, l1);
}

// ---------------- finalize (recomputes eA phases inline) ----------------
__global__ void finalize_kernel(float* __restrict__ G, const float* __restrict__ pts,
                                const float* __restrict__ W)
{
    __shared__ float red[256];
    int n = blockIdx.x, t = threadIdx.x;
    u64 base = (u64)n * TWO_D;
    float x0 = pts[3*n+0]*20.f, x1 = pts[3*n+1]*20.f, x2 = pts[3*n+2]*20.f;

    float re[2], im[2], acc = 0.f;
#pragma unroll
    for (int q = 0; q < 2; q++) {
        int j = t + q * 256;
        float ph = x0*W[j] + x1*W[DENC+j] + x2*W[2*DENC+j];
        float sA, cA; fast_sincos(ph, sA, cA);
        float Gc = G[base + j], Gs = G[base + DENC + j];
        float den = cA * cA + sA * sA;
        float r  = (Gc * cA + Gs * sA) / den;
        float ii = (Gs * cA - Gc * sA) / den;
        re[q] = r; im[q] = ii;
        acc += r * r + ii * ii;
    }
    red[t] = acc;
    __syncthreads();
#pragma unroll
    for (int s = 128; s > 0; s >>= 1) {
        if (t < s) red[t] += red[t + s];
        __syncthreads();
    }
    float scale = 22.62741699796952f / sqrtf(red[0]);   // sqrt(512)/nrm
#pragma unroll
    for (int q = 0; q < 2; q++) {
        int j = t + q * 256;
        G[base + j]        = re[q] * scale;
        G[base + DENC + j] = im[q] * scale;
    }
}

// ---------------------------------------------------------------------------
extern "C" void kernel_launch(void* const* d_in, const int* in_sizes, int n_in,
                              void* d_out, int out_size)
{
    const float* pts = (const float*)d_in[0];
    const float* A   = (const float*)d_in[1];
    const float* B   = (const float*)d_in[2];
    float* out = (float*)d_out;

    bf16 *eBh, *eBl, *eATh, *eATl, *C1Th, *C1Tl;
    float *C1p;
    cudaGetSymbolAddress((void**)&eBh,  g_eBh);
    cudaGetSymbolAddress((void**)&eBl,  g_eBl);
    cudaGetSymbolAddress((void**)&eATh, g_eATh);
    cudaGetSymbolAddress((void**)&eATl, g_eATl);
    cudaGetSymbolAddress((void**)&C1Th, g_C1Th);
    cudaGetSymbolAddress((void**)&C1Tl, g_C1Tl);
    cudaGetSymbolAddress((void**)&C1p,  g_C1p);

    const int SMEM1 = 5 * (20480 + 2 * 32 * 272);    // 189440
    const int SMEM2 = 5 * (20480 + 2 * 128 * 80);    // 204800
    cudaFuncSetAttribute(gemm_mma<1>, cudaFuncAttributeMaxDynamicSharedMemorySize, SMEM1);
    cudaFuncSetAttribute(gemm_mma<2>, cudaFuncAttributeMaxDynamicSharedMemorySize, SMEM2);

    enc_eB <<<((u64)NPTS * PDIM) / 256, 256>>>(pts, B);
    enc_eAT<<<((u64)DENC * NPTS) / 256, 256>>>(pts, A);

    // GEMM1: C1p[z] = partial over K-quarter z of eAT[d][n] * eB[n][p]
    gemm_mma<1><<<dim3(TWO_P / 128, TWO_D / 128, KSPLIT), 256, SMEM1>>>(
        eATh, eATl, eBh, eBl, C1p);
    reduce_c1<<<(TWO_D * TWO_P) / 512, 256>>>(C1p, C1Th, C1Tl);

    // GEMM2: G[n][d] = sum_p eB[n][p] * C1T[d][p]
    gemm_mma<2><<<dim3(TWO_D / 128, NPTS / 128), 256, SMEM2>>>(
        eBh, eBl, C1Th, C1Tl, out);

    finalize_kernel<<<NPTS, 256>>>(out, pts, A);
}